// round 9
// baseline (speedup 1.0000x reference)
#include <cuda_runtime.h>
#include <math.h>

#define N_ 4096
#define HD 32
#define KNUM 2048
#define SCALE 0.17677669529663687f
#define ROWS 4          // query rows per CTA
#define TKEYS 256       // keys per smem tile

// scratch (__device__ globals: allocation-free rule)
__device__ float g_qkv[768 * N_];
__device__ float g_q[8 * N_ * HD];
__device__ float g_k[8 * N_ * HD];
__device__ float g_v[8 * N_ * HD];
__device__ float g_attn[256 * N_];
__device__ float g_proj[256 * N_];

// smem layout of k_attn (float offsets)  -- total ~104.6 KB -> 2 CTAs/SM
#define SC_OFF 0            // scores [4][4096]
#define KT_OFF 16384        // tile   [256][36]
#define QS_OFF 25600        // qs     [4][32]
#define HI_OFF 25728        // hist   [4][256] (int)
#define PX_OFF 26752        // prefix [4] (uint)
#define WT_OFF 26756        // want   [4] (int)
#define PS_OFF 26760        // psum   [4][2]
#define RI_OFF 26768        // rowinv [4]
#define SM_TOT 26772

// ---------------- SGEMM: C[M][4096] = A[M][256] * B[256][4096] ----------------
__global__ void __launch_bounds__(256) k_sgemm(const float* __restrict__ A,
                                               const float* __restrict__ Bx, int mode) {
    const float* B = mode ? (const float*)g_attn : Bx;
    float* C = mode ? g_proj : g_qkv;
    __shared__ float As[64][17];
    __shared__ float Bs[16][128];
    int t = threadIdx.x;
    int bm = blockIdx.y * 64, bn = blockIdx.x * 128;
    int tr = t >> 4, tc = t & 15;
    int arow = t >> 2, akk = (t & 3) * 4;
    int brow = t >> 4, bcol = (t & 15) * 8;
    float acc[4][8];
#pragma unroll
    for (int i = 0; i < 4; i++)
#pragma unroll
        for (int j = 0; j < 8; j++) acc[i][j] = 0.f;
    for (int k0 = 0; k0 < 256; k0 += 16) {
        float4 a4 = *(const float4*)&A[(bm + arow) * 256 + k0 + akk];
        float4 b0 = *(const float4*)&B[(size_t)(k0 + brow) * N_ + bn + bcol];
        float4 b1 = *(const float4*)&B[(size_t)(k0 + brow) * N_ + bn + bcol + 4];
        __syncthreads();
        As[arow][akk + 0] = a4.x; As[arow][akk + 1] = a4.y;
        As[arow][akk + 2] = a4.z; As[arow][akk + 3] = a4.w;
        *(float4*)&Bs[brow][bcol] = b0;
        *(float4*)&Bs[brow][bcol + 4] = b1;
        __syncthreads();
#pragma unroll
        for (int k = 0; k < 16; k++) {
            float4 bv0 = *(const float4*)&Bs[k][tc * 4];
            float4 bv1 = *(const float4*)&Bs[k][64 + tc * 4];
#pragma unroll
            for (int i = 0; i < 4; i++) {
                float a = As[tr * 4 + i][k];
                acc[i][0] += a * bv0.x; acc[i][1] += a * bv0.y;
                acc[i][2] += a * bv0.z; acc[i][3] += a * bv0.w;
                acc[i][4] += a * bv1.x; acc[i][5] += a * bv1.y;
                acc[i][6] += a * bv1.z; acc[i][7] += a * bv1.w;
            }
        }
    }
#pragma unroll
    for (int i = 0; i < 4; i++) {
        size_t row = bm + tr * 4 + i;
        *(float4*)&C[row * N_ + bn + tc * 4] =
            make_float4(acc[i][0], acc[i][1], acc[i][2], acc[i][3]);
        *(float4*)&C[row * N_ + bn + 64 + tc * 4] =
            make_float4(acc[i][4], acc[i][5], acc[i][6], acc[i][7]);
    }
}

// ---------- transpose [3C][N] -> [h][n][d] with l2norm for q,k ----------
__global__ void __launch_bounds__(256) k_prep(int which) {     // 0=q 1=k 2=v
    int idx = blockIdx.x * 256 + threadIdx.x;       // h*4096+n
    int h = idx >> 12, n = idx & 4095;
    const float* src = g_qkv + (size_t)(which * 256 + h * 32) * N_ + n;
    float s[32], ss = 0.f;
#pragma unroll
    for (int d = 0; d < 32; d++) { s[d] = src[(size_t)d * N_]; ss += s[d] * s[d]; }
    float inv = 1.f;
    if (which < 2) inv = 1.f / fmaxf(sqrtf(ss), 1e-12f);
    float* dst = (which == 0 ? g_q : which == 1 ? g_k : g_v) + (size_t)idx * 32;
#pragma unroll
    for (int d = 0; d < 32; d++) dst[d] = s[d] * inv;
}

// no-op pad so ncu's (-s 5 -c 1) capture slot lands on k_attn
__global__ void k_nop() {}

// ---------------- fused attention: QK, radix topk, softmax, AV ----------------
// 4 rows/CTA, 256 threads (8 warps), 256-key tiles, 107KB smem -> 2 CTAs/SM.
__global__ void __launch_bounds__(256, 2) k_attn() {
    extern __shared__ float sm[];
    float*    scores  = sm + SC_OFF;            // [4][4096]
    float*    tile    = sm + KT_OFF;            // [256][36]
    float*    qs      = sm + QS_OFF;            // [4][32]
    int*      hist    = (int*)(sm + HI_OFF);    // [4][256]
    unsigned* sprefix = (unsigned*)(sm + PX_OFF);
    int*      swant   = (int*)(sm + WT_OFF);
    float*    psum    = sm + PS_OFF;            // [4][2]
    float*    rowinv  = sm + RI_OFF;            // [4]

    int h = blockIdx.y;
    int row0 = blockIdx.x * ROWS;
    int t = threadIdx.x, w = t >> 5, l = t & 31;
    const float* Q = g_q + (size_t)h * N_ * HD;
    const float* K = g_k + (size_t)h * N_ * HD;
    const float* V = g_v + (size_t)h * N_ * HD;

    if (t < 32) {   // 4 rows * 8 float4
        int r = t >> 3;
        ((float4*)qs)[t] = ((const float4*)(Q + (size_t)(row0 + r) * HD))[t & 7];
    }
    if (t < ROWS) { sprefix[t] = 0u; swant[t] = KNUM; }

    // ---- Phase 1: QK scores. 256-key tile; warp w -> keys [w*32, w*32+32).
    {
        const float4* src = (const float4*)K;   // 8 float4 per key
        float4 pf[8];
#pragma unroll
        for (int i = 0; i < 8; i++) pf[i] = src[t * 8 + i];
        for (int tb = 0; tb < N_; tb += TKEYS) {
            __syncthreads();
#pragma unroll
            for (int i = 0; i < 8; i++) *(float4*)&tile[t * 36 + i * 4] = pf[i];
            __syncthreads();
            if (tb + TKEYS < N_) {
                const float4* nsrc = (const float4*)(K + (size_t)(tb + TKEYS) * HD);
#pragma unroll
                for (int i = 0; i < 8; i++) pf[i] = nsrc[t * 8 + i];
            }
            int key = w * 32 + l;
            float acc[ROWS];
#pragma unroll
            for (int r = 0; r < ROWS; r++) acc[r] = 0.f;
#pragma unroll
            for (int dc = 0; dc < 8; dc++) {
                float4 kv = *(float4*)&tile[key * 36 + dc * 4];
#pragma unroll
                for (int r = 0; r < ROWS; r++) {
                    float4 qv = *(float4*)&qs[r * 32 + dc * 4];
                    acc[r] += qv.x * kv.x + qv.y * kv.y + qv.z * kv.z + qv.w * kv.w;
                }
            }
#pragma unroll
            for (int r = 0; r < ROWS; r++) {
                float s = fminf(fmaxf(acc[r] * SCALE, -32.f), 32.f);
                scores[r * N_ + tb + key] = s;
            }
        }
    }

    // ---- Phase 2: exact k-th largest per row, 4-pass radix select.
    // Row r scanned by warps 2r, 2r+1. Warp-aggregated histogram atomics.
    int r = w >> 1;
    int sub = (w & 1) * 32 + l;
    float* srow = scores + r * N_;
    for (int j = 3; j >= 0; j--) {
        for (int b = t; b < ROWS * 256; b += 256) ((int*)hist)[b] = 0;
        __syncthreads();
        unsigned prefix = sprefix[r];
        for (int i = sub; i < N_; i += 64) {
            unsigned bb = __float_as_uint(srow[i]);
            unsigned u = (bb & 0x80000000u) ? ~bb : (bb | 0x80000000u);
            bool ok = (j == 3) || ((u >> ((j + 1) * 8)) == prefix);
            unsigned bin = ok ? ((u >> (j * 8)) & 255u) : 0xFFFFFFFFu;
            unsigned peers = __match_any_sync(0xffffffffu, bin);
            if (ok && (__ffs(peers) - 1 == l))
                atomicAdd(&hist[r * 256 + bin], __popc(peers));
        }
        __syncthreads();
        if ((w & 1) == 0) {           // warp 2r selects for row r, warp-parallel
            int want = swant[r];
            int base = 255 - l * 8;   // lane l owns 8 descending bins
            int cnt[8]; int local = 0;
#pragma unroll
            for (int i = 0; i < 8; i++) { cnt[i] = hist[r * 256 + base - i]; local += cnt[i]; }
            int pre = local;
#pragma unroll
            for (int o = 1; o < 32; o <<= 1) {
                int x = __shfl_up_sync(0xffffffffu, pre, o);
                if (l >= o) pre += x;
            }
            int cum_before = pre - local;
            if (cum_before < want && cum_before + local >= want) {
                int rem = want - cum_before;
                int c = 0;
#pragma unroll
                for (int i = 0; i < 8; i++) {
                    if (c + cnt[i] >= rem) {
                        sprefix[r] = (sprefix[r] << 8) | (unsigned)(base - i);
                        swant[r] = rem - c;
                        break;
                    }
                    c += cnt[i];
                }
            }
        }
        __syncthreads();
    }
    unsigned T = sprefix[r];          // uint key of exact k-th largest

    // ---- Phase 3: masked exp + sum (no max shift needed: |s| <= 0.177)
    {
        float sum = 0.f;
        for (int i = sub; i < N_; i += 64) {
            float s = srow[i];
            unsigned bb = __float_as_uint(s);
            unsigned u = (bb & 0x80000000u) ? ~bb : (bb | 0x80000000u);
            float p = (u >= T) ? __expf(s) : 0.f;
            srow[i] = p;
            sum += p;
        }
#pragma unroll
        for (int o = 16; o; o >>= 1) sum += __shfl_xor_sync(0xffffffffu, sum, o);
        if (l == 0) psum[r * 2 + (w & 1)] = sum;
        __syncthreads();
        if (t < ROWS) rowinv[t] = 1.f / (psum[t * 2] + psum[t * 2 + 1]);
    }

    // ---- Phase 4: AV. Warp w -> keys [w*32, w*32+32) per tile.
    float acc[ROWS];
#pragma unroll
    for (int rr = 0; rr < ROWS; rr++) acc[rr] = 0.f;
    {
        const float4* src = (const float4*)V;
        float4 pf[8];
#pragma unroll
        for (int i = 0; i < 8; i++) pf[i] = src[t * 8 + i];
        for (int tb = 0; tb < N_; tb += TKEYS) {
            __syncthreads();
#pragma unroll
            for (int i = 0; i < 8; i++) *(float4*)&tile[t * 36 + i * 4] = pf[i];
            __syncthreads();
            if (tb + TKEYS < N_) {
                const float4* nsrc = (const float4*)(V + (size_t)(tb + TKEYS) * HD);
#pragma unroll
                for (int i = 0; i < 8; i++) pf[i] = nsrc[t * 8 + i];
            }
#pragma unroll
            for (int g = 0; g < 8; g++) {
                int n0 = w * 32 + g * 4;
                float4 p[ROWS];
#pragma unroll
                for (int rr = 0; rr < ROWS; rr++)
                    p[rr] = *(float4*)&scores[rr * N_ + tb + n0];
                float v0 = tile[(n0 + 0) * 36 + l];
                float v1 = tile[(n0 + 1) * 36 + l];
                float v2 = tile[(n0 + 2) * 36 + l];
                float v3 = tile[(n0 + 3) * 36 + l];
#pragma unroll
                for (int rr = 0; rr < ROWS; rr++)
                    acc[rr] += p[rr].x * v0 + p[rr].y * v1 + p[rr].z * v2 + p[rr].w * v3;
            }
        }
    }
    // cross-warp reduce partials (reuse tile: 8 warps x 4 rows x 32 dims)
    __syncthreads();
    float* red = tile;
#pragma unroll
    for (int rr = 0; rr < ROWS; rr++) red[w * 128 + rr * 32 + l] = acc[rr];
    __syncthreads();
    if (t < 128) {
        int rr = t >> 5, d = t & 31;
        float o = 0.f;
#pragma unroll
        for (int ww = 0; ww < 8; ww++) o += red[ww * 128 + rr * 32 + d];
        o *= rowinv[rr];
        g_attn[(size_t)(h * 32 + d) * N_ + row0 + rr] = o;
    }
}

// ---------------- GroupNorm(32 groups) ----------------
__global__ void __launch_bounds__(256) k_gn(const float* __restrict__ gamma,
                                            const float* __restrict__ beta,
                                            float* __restrict__ out) {
    __shared__ float rs[2][8];
    int g = blockIdx.x, t = threadIdx.x;
    const float* src = g_proj + (size_t)g * 8 * N_;
    float sum = 0.f, sq = 0.f;
    for (int i = t; i < 8 * N_; i += 256) { float v = src[i]; sum += v; sq += v * v; }
#pragma unroll
    for (int o = 16; o; o >>= 1) {
        sum += __shfl_xor_sync(0xffffffffu, sum, o);
        sq  += __shfl_xor_sync(0xffffffffu, sq, o);
    }
    if ((t & 31) == 0) { rs[0][t >> 5] = sum; rs[1][t >> 5] = sq; }
    __syncthreads();
    if (t < 32) {
        float a = (t < 8) ? rs[0][t] : 0.f;
        float b = (t < 8) ? rs[1][t] : 0.f;
#pragma unroll
        for (int o = 4; o; o >>= 1) {
            a += __shfl_xor_sync(0xffffffffu, a, o);
            b += __shfl_xor_sync(0xffffffffu, b, o);
        }
        if (t == 0) { rs[0][0] = a; rs[1][0] = b; }
    }
    __syncthreads();
    float inv_m = 1.f / (8.f * N_);
    float mean = rs[0][0] * inv_m;
    float var = rs[1][0] * inv_m - mean * mean;
    float rstd = rsqrtf(var + 1e-6f);
    for (int i = t; i < 8 * N_; i += 256) {
        int c = g * 8 + (i >> 12);
        out[(size_t)g * 8 * N_ + i] = (src[i] - mean) * rstd * gamma[c] + beta[c];
    }
}

extern "C" void kernel_launch(void* const* d_in, const int* in_sizes, int n_in,
                              void* d_out, int out_size) {
    (void)in_sizes; (void)n_in; (void)out_size;
    const float* x      = (const float*)d_in[0];
    const float* w_qkv  = (const float*)d_in[1];
    const float* w_proj = (const float*)d_in[2];
    const float* gamma  = (const float*)d_in[3];
    const float* beta   = (const float*)d_in[4];
    float* out = (float*)d_out;

    cudaFuncSetAttribute(k_attn, cudaFuncAttributeMaxDynamicSharedMemorySize,
                         SM_TOT * (int)sizeof(float));

    // launch order arranged so ncu (-s 5 -c 1) captures k_attn (index 5)
    k_sgemm<<<dim3(32, 12), 256>>>(w_qkv, x, 0);          // 0: qkv [768][4096]
    k_prep<<<128, 256>>>(0);                               // 1: q
    k_prep<<<128, 256>>>(1);                               // 2: k
    k_prep<<<128, 256>>>(2);                               // 3: v
    k_nop<<<1, 32>>>();                                    // 4: pad
    k_attn<<<dim3(1024, 8), 256, SM_TOT * sizeof(float)>>>();  // 5: ATTN (profiled)
    k_sgemm<<<dim3(32, 4), 256>>>(w_proj, nullptr, 1);     // 6: proj
    k_gn<<<32, 256>>>(gamma, beta, out);                   // 7: groupnorm
}

// round 10
// speedup vs baseline: 1.2191x; 1.2191x over previous
#include <cuda_runtime.h>
#include <math.h>

#define N_ 4096
#define HD 32
#define KNUM 2048
#define SCALE 0.17677669529663687f

// scratch (__device__ globals: allocation-free rule)
__device__ float g_qkv[768 * N_];
__device__ float g_q[8 * N_ * HD];
__device__ float g_k[8 * N_ * HD];
__device__ float g_v[8 * N_ * HD];
__device__ float g_attn[256 * N_];
__device__ float g_proj[256 * N_];

// smem layout of k_attn (float offsets)
#define SC_OFF 0            // scores [8][4096]
#define KT_OFF 32768        // tile   [512][36]
#define QS_OFF 51200        // qs     [8][32]
#define HI_OFF 51456        // hist   [8][256] (int)
#define PX_OFF 53504        // s_prefix [8] (uint)
#define WT_OFF 53512        // s_want   [8] (int)
#define PS_OFF 53520        // s_psum   [8][2]
#define RI_OFF 53536        // rowinv   [8]
#define SM_TOT 53544

// ---------------- SGEMM: C[M][4096] = A[M][256] * B[256][4096] ----------------
__global__ void __launch_bounds__(256) k_sgemm(const float* __restrict__ A,
                                               const float* __restrict__ Bx, int mode) {
    const float* B = mode ? (const float*)g_attn : Bx;
    float* C = mode ? g_proj : g_qkv;
    __shared__ float As[64][17];
    __shared__ float Bs[16][128];
    int t = threadIdx.x;
    int bm = blockIdx.y * 64, bn = blockIdx.x * 128;
    int tr = t >> 4, tc = t & 15;
    int arow = t >> 2, akk = (t & 3) * 4;
    int brow = t >> 4, bcol = (t & 15) * 8;
    float acc[4][8];
#pragma unroll
    for (int i = 0; i < 4; i++)
#pragma unroll
        for (int j = 0; j < 8; j++) acc[i][j] = 0.f;
    for (int k0 = 0; k0 < 256; k0 += 16) {
        float4 a4 = *(const float4*)&A[(bm + arow) * 256 + k0 + akk];
        float4 b0 = *(const float4*)&B[(size_t)(k0 + brow) * N_ + bn + bcol];
        float4 b1 = *(const float4*)&B[(size_t)(k0 + brow) * N_ + bn + bcol + 4];
        __syncthreads();
        As[arow][akk + 0] = a4.x; As[arow][akk + 1] = a4.y;
        As[arow][akk + 2] = a4.z; As[arow][akk + 3] = a4.w;
        *(float4*)&Bs[brow][bcol] = b0;
        *(float4*)&Bs[brow][bcol + 4] = b1;
        __syncthreads();
#pragma unroll
        for (int k = 0; k < 16; k++) {
            float4 bv0 = *(const float4*)&Bs[k][tc * 4];
            float4 bv1 = *(const float4*)&Bs[k][64 + tc * 4];
#pragma unroll
            for (int i = 0; i < 4; i++) {
                float a = As[tr * 4 + i][k];
                acc[i][0] += a * bv0.x; acc[i][1] += a * bv0.y;
                acc[i][2] += a * bv0.z; acc[i][3] += a * bv0.w;
                acc[i][4] += a * bv1.x; acc[i][5] += a * bv1.y;
                acc[i][6] += a * bv1.z; acc[i][7] += a * bv1.w;
            }
        }
    }
#pragma unroll
    for (int i = 0; i < 4; i++) {
        size_t row = bm + tr * 4 + i;
        *(float4*)&C[row * N_ + bn + tc * 4] =
            make_float4(acc[i][0], acc[i][1], acc[i][2], acc[i][3]);
        *(float4*)&C[row * N_ + bn + 64 + tc * 4] =
            make_float4(acc[i][4], acc[i][5], acc[i][6], acc[i][7]);
    }
}

// ---------- transpose [3C][N] -> [h][n][d] with l2norm for q,k ----------
__global__ void __launch_bounds__(256) k_prep() {
    int which = blockIdx.y;                         // 0=q 1=k 2=v
    int idx = blockIdx.x * 256 + threadIdx.x;       // h*4096+n
    int h = idx >> 12, n = idx & 4095;
    const float* src = g_qkv + (size_t)(which * 256 + h * 32) * N_ + n;
    float s[32], ss = 0.f;
#pragma unroll
    for (int d = 0; d < 32; d++) { s[d] = src[(size_t)d * N_]; ss += s[d] * s[d]; }
    float inv = 1.f;
    if (which < 2) inv = 1.f / fmaxf(sqrtf(ss), 1e-12f);
    float* dst = (which == 0 ? g_q : which == 1 ? g_k : g_v) + (size_t)idx * 32;
#pragma unroll
    for (int d = 0; d < 32; d++) dst[d] = s[d] * inv;
}

// no-op pad: with the harness's 2 internal pre-launches, this makes k_attn
// land exactly on ncu's skip-5 capture slot.
__global__ void k_nop() {}

// ---------------- fused attention: QK, radix topk, softmax, AV ----------------
// 512 threads (16 warps), 512-key tiles, register prefetch of next tile.
__global__ void __launch_bounds__(512) k_attn() {
    extern __shared__ float sm[];
    float*    scores  = sm + SC_OFF;            // [8][4096]
    float*    tile    = sm + KT_OFF;            // [512][36]
    float*    qs      = sm + QS_OFF;            // [8][32]
    int*      hist    = (int*)(sm + HI_OFF);    // [8][256]
    unsigned* sprefix = (unsigned*)(sm + PX_OFF);
    int*      swant   = (int*)(sm + WT_OFF);
    float*    psum    = sm + PS_OFF;            // [8][2]
    float*    rowinv  = sm + RI_OFF;            // [8]

    int h = blockIdx.y;
    int row0 = blockIdx.x * 8;
    int t = threadIdx.x, w = t >> 5, l = t & 31;
    const float* Q = g_q + (size_t)h * N_ * HD;
    const float* K = g_k + (size_t)h * N_ * HD;
    const float* V = g_v + (size_t)h * N_ * HD;

    if (t < 64) {   // 8 rows * 8 float4
        int r = t >> 3;
        ((float4*)qs)[t] = ((const float4*)(Q + (size_t)(row0 + r) * HD))[t & 7];
    }
    if (t < 8) { sprefix[t] = 0u; swant[t] = KNUM; }

    // ---- Phase 1: QK scores. Tile = 512 keys; warp w -> keys [w*32, w*32+32).
    {
        const float4* src = (const float4*)K;   // 8 float4 per key
        float4 pf[8];
#pragma unroll
        for (int i = 0; i < 8; i++) pf[i] = src[t * 8 + i];
        for (int tb = 0; tb < N_; tb += 512) {
            __syncthreads();
#pragma unroll
            for (int i = 0; i < 8; i++) *(float4*)&tile[t * 36 + i * 4] = pf[i];
            __syncthreads();
            if (tb + 512 < N_) {
                const float4* nsrc = (const float4*)(K + (size_t)(tb + 512) * HD);
#pragma unroll
                for (int i = 0; i < 8; i++) pf[i] = nsrc[t * 8 + i];
            }
            int key = w * 32 + l;
            float acc[8];
#pragma unroll
            for (int r = 0; r < 8; r++) acc[r] = 0.f;
#pragma unroll
            for (int dc = 0; dc < 8; dc++) {
                float4 kv = *(float4*)&tile[key * 36 + dc * 4];
#pragma unroll
                for (int r = 0; r < 8; r++) {
                    float4 qv = *(float4*)&qs[r * 32 + dc * 4];
                    acc[r] += qv.x * kv.x + qv.y * kv.y + qv.z * kv.z + qv.w * kv.w;
                }
            }
#pragma unroll
            for (int r = 0; r < 8; r++) {
                float s = fminf(fmaxf(acc[r] * SCALE, -32.f), 32.f);
                scores[r * N_ + tb + key] = s;
            }
        }
    }

    // ---- Phase 2: exact k-th largest per row, 4-pass radix select.
    // Rows 0..7; row r scanned by warps 2r and 2r+1 (sub-lane 0..63).
    int r = w >> 1;
    int sub = (w & 1) * 32 + l;
    float* srow = scores + r * N_;
    for (int j = 3; j >= 0; j--) {
        for (int b = t; b < 2048; b += 512) ((int*)hist)[b] = 0;
        __syncthreads();
        unsigned prefix = sprefix[r];
        for (int i = sub; i < N_; i += 64) {
            unsigned bb = __float_as_uint(srow[i]);
            unsigned u = (bb & 0x80000000u) ? ~bb : (bb | 0x80000000u);
            bool ok = (j == 3) || ((u >> ((j + 1) * 8)) == prefix);
            unsigned bin = ok ? ((u >> (j * 8)) & 255u) : 0xFFFFFFFFu;
            unsigned peers = __match_any_sync(0xffffffffu, bin);
            if (ok && (__ffs(peers) - 1 == l))
                atomicAdd(&hist[r * 256 + bin], __popc(peers));
        }
        __syncthreads();
        if ((w & 1) == 0) {           // warp 2r selects for row r, warp-parallel
            int want = swant[r];
            int base = 255 - l * 8;   // lane l owns 8 descending bins
            int cnt[8]; int local = 0;
#pragma unroll
            for (int i = 0; i < 8; i++) { cnt[i] = hist[r * 256 + base - i]; local += cnt[i]; }
            int pre = local;
#pragma unroll
            for (int o = 1; o < 32; o <<= 1) {
                int x = __shfl_up_sync(0xffffffffu, pre, o);
                if (l >= o) pre += x;
            }
            int cum_before = pre - local;   // counts in bins above this lane's chunk
            if (cum_before < want && cum_before + local >= want) {
                int rem = want - cum_before;
                int c = 0;
#pragma unroll
                for (int i = 0; i < 8; i++) {
                    if (c + cnt[i] >= rem) {
                        sprefix[r] = (sprefix[r] << 8) | (unsigned)(base - i);
                        swant[r] = rem - c;
                        break;
                    }
                    c += cnt[i];
                }
            }
        }
        __syncthreads();
    }
    unsigned T = sprefix[r];          // uint key of exact k-th largest

    // ---- Phase 3: masked exp + sum (no max shift needed: |s| <= 0.177)
    {
        float sum = 0.f;
        for (int i = sub; i < N_; i += 64) {
            float s = srow[i];
            unsigned bb = __float_as_uint(s);
            unsigned u = (bb & 0x80000000u) ? ~bb : (bb | 0x80000000u);
            float p = (u >= T) ? __expf(s) : 0.f;
            srow[i] = p;
            sum += p;
        }
#pragma unroll
        for (int o = 16; o; o >>= 1) sum += __shfl_xor_sync(0xffffffffu, sum, o);
        if (l == 0) psum[r * 2 + (w & 1)] = sum;
        __syncthreads();
        if (t < 8) rowinv[t] = 1.f / (psum[t * 2] + psum[t * 2 + 1]);
    }

    // ---- Phase 4: AV. Same tiling; warp w -> keys [w*32, w*32+32) per tile.
    float acc[8];
#pragma unroll
    for (int rr = 0; rr < 8; rr++) acc[rr] = 0.f;
    {
        const float4* src = (const float4*)V;
        float4 pf[8];
#pragma unroll
        for (int i = 0; i < 8; i++) pf[i] = src[t * 8 + i];
        for (int tb = 0; tb < N_; tb += 512) {
            __syncthreads();
#pragma unroll
            for (int i = 0; i < 8; i++) *(float4*)&tile[t * 36 + i * 4] = pf[i];
            __syncthreads();
            if (tb + 512 < N_) {
                const float4* nsrc = (const float4*)(V + (size_t)(tb + 512) * HD);
#pragma unroll
                for (int i = 0; i < 8; i++) pf[i] = nsrc[t * 8 + i];
            }
#pragma unroll
            for (int g = 0; g < 8; g++) {
                int n0 = w * 32 + g * 4;
                float4 p[8];
#pragma unroll
                for (int rr = 0; rr < 8; rr++)
                    p[rr] = *(float4*)&scores[rr * N_ + tb + n0];
                float v0 = tile[(n0 + 0) * 36 + l];
                float v1 = tile[(n0 + 1) * 36 + l];
                float v2 = tile[(n0 + 2) * 36 + l];
                float v3 = tile[(n0 + 3) * 36 + l];
#pragma unroll
                for (int rr = 0; rr < 8; rr++)
                    acc[rr] += p[rr].x * v0 + p[rr].y * v1 + p[rr].z * v2 + p[rr].w * v3;
            }
        }
    }
    // cross-warp reduce partials (reuse tile buffer: 16 warps x 8 rows x 32 dims)
    __syncthreads();
    float* red = tile;
#pragma unroll
    for (int rr = 0; rr < 8; rr++) red[w * 256 + rr * 32 + l] = acc[rr];
    __syncthreads();
    if (t < 256) {
        int rr = t >> 5, d = t & 31;
        float o = 0.f;
#pragma unroll
        for (int ww = 0; ww < 16; ww++) o += red[ww * 256 + rr * 32 + d];
        o *= rowinv[rr];
        g_attn[(size_t)(h * 32 + d) * N_ + row0 + rr] = o;
    }
}

// ---------------- GroupNorm(32 groups) ----------------
__global__ void __launch_bounds__(256) k_gn(const float* __restrict__ gamma,
                                            const float* __restrict__ beta,
                                            float* __restrict__ out) {
    __shared__ float rs[2][8];
    int g = blockIdx.x, t = threadIdx.x;
    const float* src = g_proj + (size_t)g * 8 * N_;
    float sum = 0.f, sq = 0.f;
    for (int i = t; i < 8 * N_; i += 256) { float v = src[i]; sum += v; sq += v * v; }
#pragma unroll
    for (int o = 16; o; o >>= 1) {
        sum += __shfl_xor_sync(0xffffffffu, sum, o);
        sq  += __shfl_xor_sync(0xffffffffu, sq, o);
    }
    if ((t & 31) == 0) { rs[0][t >> 5] = sum; rs[1][t >> 5] = sq; }
    __syncthreads();
    if (t < 32) {
        float a = (t < 8) ? rs[0][t] : 0.f;
        float b = (t < 8) ? rs[1][t] : 0.f;
#pragma unroll
        for (int o = 4; o; o >>= 1) {
            a += __shfl_xor_sync(0xffffffffu, a, o);
            b += __shfl_xor_sync(0xffffffffu, b, o);
        }
        if (t == 0) { rs[0][0] = a; rs[1][0] = b; }
    }
    __syncthreads();
    float inv_m = 1.f / (8.f * N_);
    float mean = rs[0][0] * inv_m;
    float var = rs[1][0] * inv_m - mean * mean;
    float rstd = rsqrtf(var + 1e-6f);
    for (int i = t; i < 8 * N_; i += 256) {
        int c = g * 8 + (i >> 12);
        out[(size_t)g * 8 * N_ + i] = (src[i] - mean) * rstd * gamma[c] + beta[c];
    }
}

extern "C" void kernel_launch(void* const* d_in, const int* in_sizes, int n_in,
                              void* d_out, int out_size) {
    (void)in_sizes; (void)n_in; (void)out_size;
    const float* x      = (const float*)d_in[0];
    const float* w_qkv  = (const float*)d_in[1];
    const float* w_proj = (const float*)d_in[2];
    const float* gamma  = (const float*)d_in[3];
    const float* beta   = (const float*)d_in[4];
    float* out = (float*)d_out;

    cudaFuncSetAttribute(k_attn, cudaFuncAttributeMaxDynamicSharedMemorySize,
                         SM_TOT * (int)sizeof(float));

    // harness issues 2 internal launches first; ncu -s 5 captures global
    // index 5 = my index 3 -> k_attn.
    k_sgemm<<<dim3(32, 12), 256>>>(w_qkv, x, 0);               // my 0
    k_prep<<<dim3(128, 3), 256>>>();                            // my 1
    k_nop<<<1, 32>>>();                                         // my 2
    k_attn<<<dim3(512, 8), 512, SM_TOT * sizeof(float)>>>();    // my 3 (profiled)
    k_sgemm<<<dim3(32, 4), 256>>>(w_proj, nullptr, 1);          // my 4
    k_gn<<<32, 256>>>(gamma, beta, out);                        // my 5
}

// round 11
// speedup vs baseline: 1.7968x; 1.4739x over previous
#include <cuda_runtime.h>
#include <math.h>

#define N_ 4096
#define HD 32
#define KNUM 2048
#define SCALE 0.17677669529663687f

// scratch (__device__ globals: allocation-free rule)
__device__ float g_qkv[768 * N_];
__device__ float g_q[8 * N_ * HD];
__device__ float g_k[8 * N_ * HD];
__device__ float g_v[8 * N_ * HD];
__device__ float g_attn[256 * N_];
__device__ float g_proj[256 * N_];

// smem layout of k_attn (float offsets)
#define SC_OFF 0            // scores [8][4096]
#define KT_OFF 32768        // tile   [512][36]
#define QS_OFF 51200        // qs     [8][32]
#define HI_OFF 51456        // hist   [8][256] (int)
#define PX_OFF 53504        // s_prefix [8] (uint)
#define WT_OFF 53512        // s_want   [8] (int)
#define PS_OFF 53520        // s_psum   [8][2]
#define RI_OFF 53536        // rowinv   [8]
#define SM_TOT 53544

// ---------------- SGEMM: C[M][4096] = A[M][256] * B[256][4096] ----------------
__global__ void __launch_bounds__(256) k_sgemm(const float* __restrict__ A,
                                               const float* __restrict__ Bx, int mode) {
    const float* B = mode ? (const float*)g_attn : Bx;
    float* C = mode ? g_proj : g_qkv;
    __shared__ float As[64][17];
    __shared__ float Bs[16][128];
    int t = threadIdx.x;
    int bm = blockIdx.y * 64, bn = blockIdx.x * 128;
    int tr = t >> 4, tc = t & 15;
    int arow = t >> 2, akk = (t & 3) * 4;
    int brow = t >> 4, bcol = (t & 15) * 8;
    float acc[4][8];
#pragma unroll
    for (int i = 0; i < 4; i++)
#pragma unroll
        for (int j = 0; j < 8; j++) acc[i][j] = 0.f;
    for (int k0 = 0; k0 < 256; k0 += 16) {
        float4 a4 = *(const float4*)&A[(bm + arow) * 256 + k0 + akk];
        float4 b0 = *(const float4*)&B[(size_t)(k0 + brow) * N_ + bn + bcol];
        float4 b1 = *(const float4*)&B[(size_t)(k0 + brow) * N_ + bn + bcol + 4];
        __syncthreads();
        As[arow][akk + 0] = a4.x; As[arow][akk + 1] = a4.y;
        As[arow][akk + 2] = a4.z; As[arow][akk + 3] = a4.w;
        *(float4*)&Bs[brow][bcol] = b0;
        *(float4*)&Bs[brow][bcol + 4] = b1;
        __syncthreads();
#pragma unroll
        for (int k = 0; k < 16; k++) {
            float4 bv0 = *(const float4*)&Bs[k][tc * 4];
            float4 bv1 = *(const float4*)&Bs[k][64 + tc * 4];
#pragma unroll
            for (int i = 0; i < 4; i++) {
                float a = As[tr * 4 + i][k];
                acc[i][0] += a * bv0.x; acc[i][1] += a * bv0.y;
                acc[i][2] += a * bv0.z; acc[i][3] += a * bv0.w;
                acc[i][4] += a * bv1.x; acc[i][5] += a * bv1.y;
                acc[i][6] += a * bv1.z; acc[i][7] += a * bv1.w;
            }
        }
    }
#pragma unroll
    for (int i = 0; i < 4; i++) {
        size_t row = bm + tr * 4 + i;
        *(float4*)&C[row * N_ + bn + tc * 4] =
            make_float4(acc[i][0], acc[i][1], acc[i][2], acc[i][3]);
        *(float4*)&C[row * N_ + bn + 64 + tc * 4] =
            make_float4(acc[i][4], acc[i][5], acc[i][6], acc[i][7]);
    }
}

// ---------- transpose [3C][N] -> [h][n][d] with l2norm for q,k ----------
__global__ void __launch_bounds__(256) k_prep() {
    int which = blockIdx.y;                         // 0=q 1=k 2=v
    int idx = blockIdx.x * 256 + threadIdx.x;       // h*4096+n
    int h = idx >> 12, n = idx & 4095;
    const float* src = g_qkv + (size_t)(which * 256 + h * 32) * N_ + n;
    float s[32], ss = 0.f;
#pragma unroll
    for (int d = 0; d < 32; d++) { s[d] = src[(size_t)d * N_]; ss += s[d] * s[d]; }
    float inv = 1.f;
    if (which < 2) inv = 1.f / fmaxf(sqrtf(ss), 1e-12f);
    float* dst = (which == 0 ? g_q : which == 1 ? g_k : g_v) + (size_t)idx * 32;
#pragma unroll
    for (int d = 0; d < 32; d++) dst[d] = s[d] * inv;
}

// no-op pad: keeps k_attn on ncu's skip-5 capture slot (harness pre-launches 2).
__global__ void k_nop() {}

// ---------------- fused attention: QK, radix topk, softmax, AV ----------------
// 512 threads (16 warps), 512-key tiles.
// Tile gmem loads are LINEAR-COALESCED (lane-consecutive float4 -> 4 lines/LDG)
// then scattered to the [key][36] smem layout; compute side unchanged.
__global__ void __launch_bounds__(512) k_attn() {
    extern __shared__ float sm[];
    float*    scores  = sm + SC_OFF;            // [8][4096]
    float*    tile    = sm + KT_OFF;            // [512][36]
    float*    qs      = sm + QS_OFF;            // [8][32]
    int*      hist    = (int*)(sm + HI_OFF);    // [8][256]
    unsigned* sprefix = (unsigned*)(sm + PX_OFF);
    int*      swant   = (int*)(sm + WT_OFF);
    float*    psum    = sm + PS_OFF;            // [8][2]
    float*    rowinv  = sm + RI_OFF;            // [8]

    int h = blockIdx.y;
    int row0 = blockIdx.x * 8;
    int t = threadIdx.x, w = t >> 5, l = t & 31;
    const float* Q = g_q + (size_t)h * N_ * HD;
    const float* K = g_k + (size_t)h * N_ * HD;
    const float* V = g_v + (size_t)h * N_ * HD;

    // coalesced->scatter mapping for tile loads: j = i*512 + t
    // key = j>>3, dc = j&7 ; STS.128 conflict-free per quarter-warp
    int st_key = t >> 3, st_dc = t & 7;

    if (t < 64) {   // 8 rows * 8 float4
        int r = t >> 3;
        ((float4*)qs)[t] = ((const float4*)(Q + (size_t)(row0 + r) * HD))[t & 7];
    }
    if (t < 8) { sprefix[t] = 0u; swant[t] = KNUM; }

    // ---- Phase 1: QK scores. Tile = 512 keys; warp w -> keys [w*32, w*32+32).
    {
        const float4* src = (const float4*)K;   // 8 float4 per key; tile = 4096 f4
        float4 pf[8];
#pragma unroll
        for (int i = 0; i < 8; i++) pf[i] = src[i * 512 + t];          // coalesced
        for (int tb = 0; tb < N_; tb += 512) {
            __syncthreads();
#pragma unroll
            for (int i = 0; i < 8; i++)
                *(float4*)&tile[(i * 64 + st_key) * 36 + st_dc * 4] = pf[i];
            __syncthreads();
            if (tb + 512 < N_) {
                const float4* nsrc = src + (size_t)(tb + 512) * 8;
#pragma unroll
                for (int i = 0; i < 8; i++) pf[i] = nsrc[i * 512 + t]; // coalesced
            }
            int key = w * 32 + l;
            float acc[8];
#pragma unroll
            for (int r = 0; r < 8; r++) acc[r] = 0.f;
#pragma unroll
            for (int dc = 0; dc < 8; dc++) {
                float4 kv = *(float4*)&tile[key * 36 + dc * 4];
#pragma unroll
                for (int r = 0; r < 8; r++) {
                    float4 qv = *(float4*)&qs[r * 32 + dc * 4];
                    acc[r] += qv.x * kv.x + qv.y * kv.y + qv.z * kv.z + qv.w * kv.w;
                }
            }
#pragma unroll
            for (int r = 0; r < 8; r++) {
                float s = fminf(fmaxf(acc[r] * SCALE, -32.f), 32.f);
                scores[r * N_ + tb + key] = s;
            }
        }
    }

    // ---- Phase 2: exact k-th largest per row, 4-pass radix select.
    // Rows 0..7; row r scanned by warps 2r and 2r+1 (sub-lane 0..63).
    int r = w >> 1;
    int sub = (w & 1) * 32 + l;
    float* srow = scores + r * N_;
    for (int j = 3; j >= 0; j--) {
        for (int b = t; b < 2048; b += 512) ((int*)hist)[b] = 0;
        __syncthreads();
        unsigned prefix = sprefix[r];
        for (int i = sub; i < N_; i += 64) {
            unsigned bb = __float_as_uint(srow[i]);
            unsigned u = (bb & 0x80000000u) ? ~bb : (bb | 0x80000000u);
            bool ok = (j == 3) || ((u >> ((j + 1) * 8)) == prefix);
            unsigned bin = ok ? ((u >> (j * 8)) & 255u) : 0xFFFFFFFFu;
            unsigned peers = __match_any_sync(0xffffffffu, bin);
            if (ok && (__ffs(peers) - 1 == l))
                atomicAdd(&hist[r * 256 + bin], __popc(peers));
        }
        __syncthreads();
        if ((w & 1) == 0) {           // warp 2r selects for row r, warp-parallel
            int want = swant[r];
            int base = 255 - l * 8;   // lane l owns 8 descending bins
            int cnt[8]; int local = 0;
#pragma unroll
            for (int i = 0; i < 8; i++) { cnt[i] = hist[r * 256 + base - i]; local += cnt[i]; }
            int pre = local;
#pragma unroll
            for (int o = 1; o < 32; o <<= 1) {
                int x = __shfl_up_sync(0xffffffffu, pre, o);
                if (l >= o) pre += x;
            }
            int cum_before = pre - local;   // counts in bins above this lane's chunk
            if (cum_before < want && cum_before + local >= want) {
                int rem = want - cum_before;
                int c = 0;
#pragma unroll
                for (int i = 0; i < 8; i++) {
                    if (c + cnt[i] >= rem) {
                        sprefix[r] = (sprefix[r] << 8) | (unsigned)(base - i);
                        swant[r] = rem - c;
                        break;
                    }
                    c += cnt[i];
                }
            }
        }
        __syncthreads();
    }
    unsigned T = sprefix[r];          // uint key of exact k-th largest

    // ---- Phase 3: masked exp + sum (no max shift needed: |s| <= 0.177)
    {
        float sum = 0.f;
        for (int i = sub; i < N_; i += 64) {
            float s = srow[i];
            unsigned bb = __float_as_uint(s);
            unsigned u = (bb & 0x80000000u) ? ~bb : (bb | 0x80000000u);
            float p = (u >= T) ? __expf(s) : 0.f;
            srow[i] = p;
            sum += p;
        }
#pragma unroll
        for (int o = 16; o; o >>= 1) sum += __shfl_xor_sync(0xffffffffu, sum, o);
        if (l == 0) psum[r * 2 + (w & 1)] = sum;
        __syncthreads();
        if (t < 8) rowinv[t] = 1.f / (psum[t * 2] + psum[t * 2 + 1]);
    }

    // ---- Phase 4: AV. Same tiling; warp w -> keys [w*32, w*32+32) per tile.
    float acc[8];
#pragma unroll
    for (int rr = 0; rr < 8; rr++) acc[rr] = 0.f;
    {
        const float4* src = (const float4*)V;
        float4 pf[8];
#pragma unroll
        for (int i = 0; i < 8; i++) pf[i] = src[i * 512 + t];          // coalesced
        for (int tb = 0; tb < N_; tb += 512) {
            __syncthreads();
#pragma unroll
            for (int i = 0; i < 8; i++)
                *(float4*)&tile[(i * 64 + st_key) * 36 + st_dc * 4] = pf[i];
            __syncthreads();
            if (tb + 512 < N_) {
                const float4* nsrc = src + (size_t)(tb + 512) * 8;
#pragma unroll
                for (int i = 0; i < 8; i++) pf[i] = nsrc[i * 512 + t]; // coalesced
            }
#pragma unroll
            for (int g = 0; g < 8; g++) {
                int n0 = w * 32 + g * 4;
                float4 p[8];
#pragma unroll
                for (int rr = 0; rr < 8; rr++)
                    p[rr] = *(float4*)&scores[rr * N_ + tb + n0];
                float v0 = tile[(n0 + 0) * 36 + l];
                float v1 = tile[(n0 + 1) * 36 + l];
                float v2 = tile[(n0 + 2) * 36 + l];
                float v3 = tile[(n0 + 3) * 36 + l];
#pragma unroll
                for (int rr = 0; rr < 8; rr++)
                    acc[rr] += p[rr].x * v0 + p[rr].y * v1 + p[rr].z * v2 + p[rr].w * v3;
            }
        }
    }
    // cross-warp reduce partials (reuse tile buffer: 16 warps x 8 rows x 32 dims)
    __syncthreads();
    float* red = tile;
#pragma unroll
    for (int rr = 0; rr < 8; rr++) red[w * 256 + rr * 32 + l] = acc[rr];
    __syncthreads();
    if (t < 256) {
        int rr = t >> 5, d = t & 31;
        float o = 0.f;
#pragma unroll
        for (int ww = 0; ww < 16; ww++) o += red[ww * 256 + rr * 32 + d];
        o *= rowinv[rr];
        g_attn[(size_t)(h * 32 + d) * N_ + row0 + rr] = o;
    }
}

// ---------------- GroupNorm(32 groups) ----------------
__global__ void __launch_bounds__(256) k_gn(const float* __restrict__ gamma,
                                            const float* __restrict__ beta,
                                            float* __restrict__ out) {
    __shared__ float rs[2][8];
    int g = blockIdx.x, t = threadIdx.x;
    const float* src = g_proj + (size_t)g * 8 * N_;
    float sum = 0.f, sq = 0.f;
    for (int i = t; i < 8 * N_; i += 256) { float v = src[i]; sum += v; sq += v * v; }
#pragma unroll
    for (int o = 16; o; o >>= 1) {
        sum += __shfl_xor_sync(0xffffffffu, sum, o);
        sq  += __shfl_xor_sync(0xffffffffu, sq, o);
    }
    if ((t & 31) == 0) { rs[0][t >> 5] = sum; rs[1][t >> 5] = sq; }
    __syncthreads();
    if (t < 32) {
        float a = (t < 8) ? rs[0][t] : 0.f;
        float b = (t < 8) ? rs[1][t] : 0.f;
#pragma unroll
        for (int o = 4; o; o >>= 1) {
            a += __shfl_xor_sync(0xffffffffu, a, o);
            b += __shfl_xor_sync(0xffffffffu, b, o);
        }
        if (t == 0) { rs[0][0] = a; rs[1][0] = b; }
    }
    __syncthreads();
    float inv_m = 1.f / (8.f * N_);
    float mean = rs[0][0] * inv_m;
    float var = rs[1][0] * inv_m - mean * mean;
    float rstd = rsqrtf(var + 1e-6f);
    for (int i = t; i < 8 * N_; i += 256) {
        int c = g * 8 + (i >> 12);
        out[(size_t)g * 8 * N_ + i] = (src[i] - mean) * rstd * gamma[c] + beta[c];
    }
}

extern "C" void kernel_launch(void* const* d_in, const int* in_sizes, int n_in,
                              void* d_out, int out_size) {
    (void)in_sizes; (void)n_in; (void)out_size;
    const float* x      = (const float*)d_in[0];
    const float* w_qkv  = (const float*)d_in[1];
    const float* w_proj = (const float*)d_in[2];
    const float* gamma  = (const float*)d_in[3];
    const float* beta   = (const float*)d_in[4];
    float* out = (float*)d_out;

    cudaFuncSetAttribute(k_attn, cudaFuncAttributeMaxDynamicSharedMemorySize,
                         SM_TOT * (int)sizeof(float));

    // harness issues 2 internal launches first; ncu -s 5 captures global
    // index 5 = my index 3 -> k_attn.
    k_sgemm<<<dim3(32, 12), 256>>>(w_qkv, x, 0);               // my 0
    k_prep<<<dim3(128, 3), 256>>>();                            // my 1
    k_nop<<<1, 32>>>();                                         // my 2
    k_attn<<<dim3(512, 8), 512, SM_TOT * sizeof(float)>>>();    // my 3 (profiled)
    k_sgemm<<<dim3(32, 4), 256>>>(w_proj, nullptr, 1);          // my 4
    k_gn<<<32, 256>>>(gamma, beta, out);                        // my 5
}

// round 12
// speedup vs baseline: 1.9417x; 1.0807x over previous
#include <cuda_runtime.h>
#include <math.h>

#define N_ 4096
#define HD 32
#define KNUM 2048
#define SCALE 0.17677669529663687f

// scratch (__device__ globals: allocation-free rule)
__device__ float g_qkv[768 * N_];
__device__ float g_q[8 * N_ * HD];
__device__ float g_k[8 * N_ * HD];
__device__ float g_v[8 * N_ * HD];
__device__ float g_attn[256 * N_];
__device__ float g_proj[256 * N_];

// smem layout of k_attn (float offsets)
#define SC_OFF 0            // scores [8][4096]  (u-mapped uint in P1/P2, p after P3)
#define KT_OFF 32768        // tile   [512][36]
#define QS_OFF 51200        // qs     [8][32]
#define HI_OFF 51456        // hist   [8][256] (int)
#define PX_OFF 53504        // s_prefix [8] (uint)
#define WT_OFF 53512        // s_want   [8] (int)
#define PS_OFF 53520        // s_psum   [8][2]
#define RI_OFF 53536        // rowinv   [8]
#define SM_TOT 53544

// ---------------- SGEMM: C[M][4096] = A[M][256] * B[256][4096] ----------------
__global__ void __launch_bounds__(256) k_sgemm(const float* __restrict__ A,
                                               const float* __restrict__ Bx, int mode) {
    const float* B = mode ? (const float*)g_attn : Bx;
    float* C = mode ? g_proj : g_qkv;
    __shared__ float As[64][17];
    __shared__ float Bs[16][128];
    int t = threadIdx.x;
    int bm = blockIdx.y * 64, bn = blockIdx.x * 128;
    int tr = t >> 4, tc = t & 15;
    int arow = t >> 2, akk = (t & 3) * 4;
    int brow = t >> 4, bcol = (t & 15) * 8;
    float acc[4][8];
#pragma unroll
    for (int i = 0; i < 4; i++)
#pragma unroll
        for (int j = 0; j < 8; j++) acc[i][j] = 0.f;
    for (int k0 = 0; k0 < 256; k0 += 16) {
        float4 a4 = *(const float4*)&A[(bm + arow) * 256 + k0 + akk];
        float4 b0 = *(const float4*)&B[(size_t)(k0 + brow) * N_ + bn + bcol];
        float4 b1 = *(const float4*)&B[(size_t)(k0 + brow) * N_ + bn + bcol + 4];
        __syncthreads();
        As[arow][akk + 0] = a4.x; As[arow][akk + 1] = a4.y;
        As[arow][akk + 2] = a4.z; As[arow][akk + 3] = a4.w;
        *(float4*)&Bs[brow][bcol] = b0;
        *(float4*)&Bs[brow][bcol + 4] = b1;
        __syncthreads();
#pragma unroll
        for (int k = 0; k < 16; k++) {
            float4 bv0 = *(const float4*)&Bs[k][tc * 4];
            float4 bv1 = *(const float4*)&Bs[k][64 + tc * 4];
#pragma unroll
            for (int i = 0; i < 4; i++) {
                float a = As[tr * 4 + i][k];
                acc[i][0] += a * bv0.x; acc[i][1] += a * bv0.y;
                acc[i][2] += a * bv0.z; acc[i][3] += a * bv0.w;
                acc[i][4] += a * bv1.x; acc[i][5] += a * bv1.y;
                acc[i][6] += a * bv1.z; acc[i][7] += a * bv1.w;
            }
        }
    }
#pragma unroll
    for (int i = 0; i < 4; i++) {
        size_t row = bm + tr * 4 + i;
        *(float4*)&C[row * N_ + bn + tc * 4] =
            make_float4(acc[i][0], acc[i][1], acc[i][2], acc[i][3]);
        *(float4*)&C[row * N_ + bn + 64 + tc * 4] =
            make_float4(acc[i][4], acc[i][5], acc[i][6], acc[i][7]);
    }
}

// ---------- transpose [3C][N] -> [h][n][d] with l2norm for q,k ----------
__global__ void __launch_bounds__(256) k_prep() {
    int which = blockIdx.y;                         // 0=q 1=k 2=v
    int idx = blockIdx.x * 256 + threadIdx.x;       // h*4096+n
    int h = idx >> 12, n = idx & 4095;
    const float* src = g_qkv + (size_t)(which * 256 + h * 32) * N_ + n;
    float s[32], ss = 0.f;
#pragma unroll
    for (int d = 0; d < 32; d++) { s[d] = src[(size_t)d * N_]; ss += s[d] * s[d]; }
    float inv = 1.f;
    if (which < 2) inv = 1.f / fmaxf(sqrtf(ss), 1e-12f);
    float* dst = (which == 0 ? g_q : which == 1 ? g_k : g_v) + (size_t)idx * 32;
#pragma unroll
    for (int d = 0; d < 32; d++) dst[d] = s[d] * inv;
}

// no-op pad: keeps k_attn on ncu's skip-5 capture slot (harness pre-launches 2).
__global__ void k_nop() {}

// ---------------- fused attention: QK, radix topk, softmax, AV ----------------
// 512 threads (16 warps), 512-key tiles, coalesced tile loads.
// Scores stored as monotone-mapped uints (P1) -> radix passes read u directly;
// P3 inverts, masks, exps in place. P2/P3 scans batched x4 for LDS-latency ILP.
__global__ void __launch_bounds__(512) k_attn() {
    extern __shared__ float sm[];
    float*    scores  = sm + SC_OFF;            // [8][4096]
    float*    tile    = sm + KT_OFF;            // [512][36]
    float*    qs      = sm + QS_OFF;            // [8][32]
    int*      hist    = (int*)(sm + HI_OFF);    // [8][256]
    unsigned* sprefix = (unsigned*)(sm + PX_OFF);
    int*      swant   = (int*)(sm + WT_OFF);
    float*    psum    = sm + PS_OFF;            // [8][2]
    float*    rowinv  = sm + RI_OFF;            // [8]

    int h = blockIdx.y;
    int row0 = blockIdx.x * 8;
    int t = threadIdx.x, w = t >> 5, l = t & 31;
    const float* Q = g_q + (size_t)h * N_ * HD;
    const float* K = g_k + (size_t)h * N_ * HD;
    const float* V = g_v + (size_t)h * N_ * HD;

    // coalesced->scatter mapping for tile loads
    int st_key = t >> 3, st_dc = t & 7;

    if (t < 64) {   // 8 rows * 8 float4
        int r = t >> 3;
        ((float4*)qs)[t] = ((const float4*)(Q + (size_t)(row0 + r) * HD))[t & 7];
    }
    if (t < 8) { sprefix[t] = 0u; swant[t] = KNUM; }

    // ---- Phase 1: QK scores -> u-mapped uints in smem.
    {
        const float4* src = (const float4*)K;
        float4 pf[8];
#pragma unroll
        for (int i = 0; i < 8; i++) pf[i] = src[i * 512 + t];          // coalesced
        for (int tb = 0; tb < N_; tb += 512) {
            __syncthreads();
#pragma unroll
            for (int i = 0; i < 8; i++)
                *(float4*)&tile[(i * 64 + st_key) * 36 + st_dc * 4] = pf[i];
            __syncthreads();
            if (tb + 512 < N_) {
                const float4* nsrc = src + (size_t)(tb + 512) * 8;
#pragma unroll
                for (int i = 0; i < 8; i++) pf[i] = nsrc[i * 512 + t];
            }
            int key = w * 32 + l;
            float acc[8];
#pragma unroll
            for (int r = 0; r < 8; r++) acc[r] = 0.f;
#pragma unroll
            for (int dc = 0; dc < 8; dc++) {
                float4 kv = *(float4*)&tile[key * 36 + dc * 4];
#pragma unroll
                for (int r = 0; r < 8; r++) {
                    float4 qv = *(float4*)&qs[r * 32 + dc * 4];
                    acc[r] += qv.x * kv.x + qv.y * kv.y + qv.z * kv.z + qv.w * kv.w;
                }
            }
#pragma unroll
            for (int r = 0; r < 8; r++) {
                float s = fminf(fmaxf(acc[r] * SCALE, -32.f), 32.f);
                unsigned bb = __float_as_uint(s);
                unsigned u = (bb & 0x80000000u) ? ~bb : (bb | 0x80000000u);
                ((unsigned*)scores)[r * N_ + tb + key] = u;
            }
        }
    }

    // ---- Phase 2: exact k-th largest per row, 4-pass radix select on u.
    // Row r scanned by warps 2r, 2r+1 (sub-lane 0..63), x4 batched loads.
    int r = w >> 1;
    int sub = (w & 1) * 32 + l;
    unsigned* urow = (unsigned*)scores + r * N_;
    for (int j = 3; j >= 0; j--) {
        for (int b = t; b < 2048; b += 512) ((int*)hist)[b] = 0;
        __syncthreads();
        unsigned prefix = sprefix[r];
        for (int i0 = sub; i0 < N_; i0 += 256) {
            unsigned uu[4];
#pragma unroll
            for (int q4 = 0; q4 < 4; q4++) uu[q4] = urow[i0 + q4 * 64];
#pragma unroll
            for (int q4 = 0; q4 < 4; q4++) {
                unsigned u = uu[q4];
                bool ok = (j == 3) || ((u >> ((j + 1) * 8)) == prefix);
                unsigned bin = ok ? ((u >> (j * 8)) & 255u) : 0xFFFFFFFFu;
                unsigned peers = __match_any_sync(0xffffffffu, bin);
                if (ok && (__ffs(peers) - 1 == l))
                    atomicAdd(&hist[r * 256 + bin], __popc(peers));
            }
        }
        __syncthreads();
        if ((w & 1) == 0) {           // warp 2r selects for row r, warp-parallel
            int want = swant[r];
            int base = 255 - l * 8;   // lane l owns 8 descending bins
            int cnt[8]; int local = 0;
#pragma unroll
            for (int i = 0; i < 8; i++) { cnt[i] = hist[r * 256 + base - i]; local += cnt[i]; }
            int pre = local;
#pragma unroll
            for (int o = 1; o < 32; o <<= 1) {
                int x = __shfl_up_sync(0xffffffffu, pre, o);
                if (l >= o) pre += x;
            }
            int cum_before = pre - local;
            if (cum_before < want && cum_before + local >= want) {
                int rem = want - cum_before;
                int c = 0;
#pragma unroll
                for (int i = 0; i < 8; i++) {
                    if (c + cnt[i] >= rem) {
                        sprefix[r] = (sprefix[r] << 8) | (unsigned)(base - i);
                        swant[r] = rem - c;
                        break;
                    }
                    c += cnt[i];
                }
            }
        }
        __syncthreads();
    }
    unsigned T = sprefix[r];          // uint key of exact k-th largest

    // ---- Phase 3: invert map, mask, exp, sum (|s|<=0.177: no max shift).
    {
        float sum = 0.f;
        for (int i0 = sub; i0 < N_; i0 += 256) {
            unsigned uu[4];
#pragma unroll
            for (int q4 = 0; q4 < 4; q4++) uu[q4] = urow[i0 + q4 * 64];
            float pp[4];
#pragma unroll
            for (int q4 = 0; q4 < 4; q4++) {
                unsigned u = uu[q4];
                unsigned bb = (u & 0x80000000u) ? (u & 0x7FFFFFFFu) : ~u;
                float s = __uint_as_float(bb);
                pp[q4] = (u >= T) ? __expf(s) : 0.f;
                sum += pp[q4];
            }
#pragma unroll
            for (int q4 = 0; q4 < 4; q4++)
                ((float*)urow)[i0 + q4 * 64] = pp[q4];
        }
#pragma unroll
        for (int o = 16; o; o >>= 1) sum += __shfl_xor_sync(0xffffffffu, sum, o);
        if (l == 0) psum[r * 2 + (w & 1)] = sum;
        __syncthreads();
        if (t < 8) rowinv[t] = 1.f / (psum[t * 2] + psum[t * 2 + 1]);
    }

    // ---- Phase 4: AV. Warp w -> keys [w*32, w*32+32) per tile.
    float acc[8];
#pragma unroll
    for (int rr = 0; rr < 8; rr++) acc[rr] = 0.f;
    {
        const float4* src = (const float4*)V;
        float4 pf[8];
#pragma unroll
        for (int i = 0; i < 8; i++) pf[i] = src[i * 512 + t];          // coalesced
        for (int tb = 0; tb < N_; tb += 512) {
            __syncthreads();
#pragma unroll
            for (int i = 0; i < 8; i++)
                *(float4*)&tile[(i * 64 + st_key) * 36 + st_dc * 4] = pf[i];
            __syncthreads();
            if (tb + 512 < N_) {
                const float4* nsrc = src + (size_t)(tb + 512) * 8;
#pragma unroll
                for (int i = 0; i < 8; i++) pf[i] = nsrc[i * 512 + t];
            }
#pragma unroll
            for (int g = 0; g < 8; g++) {
                int n0 = w * 32 + g * 4;
                float4 p[8];
#pragma unroll
                for (int rr = 0; rr < 8; rr++)
                    p[rr] = *(float4*)&scores[rr * N_ + tb + n0];
                float v0 = tile[(n0 + 0) * 36 + l];
                float v1 = tile[(n0 + 1) * 36 + l];
                float v2 = tile[(n0 + 2) * 36 + l];
                float v3 = tile[(n0 + 3) * 36 + l];
#pragma unroll
                for (int rr = 0; rr < 8; rr++)
                    acc[rr] += p[rr].x * v0 + p[rr].y * v1 + p[rr].z * v2 + p[rr].w * v3;
            }
        }
    }
    // cross-warp reduce partials (reuse tile buffer: 16 warps x 8 rows x 32 dims)
    __syncthreads();
    float* red = tile;
#pragma unroll
    for (int rr = 0; rr < 8; rr++) red[w * 256 + rr * 32 + l] = acc[rr];
    __syncthreads();
    if (t < 256) {
        int rr = t >> 5, d = t & 31;
        float o = 0.f;
#pragma unroll
        for (int ww = 0; ww < 16; ww++) o += red[ww * 256 + rr * 32 + d];
        o *= rowinv[rr];
        g_attn[(size_t)(h * 32 + d) * N_ + row0 + rr] = o;
    }
}

// ---------------- GroupNorm(32 groups) ----------------
__global__ void __launch_bounds__(256) k_gn(const float* __restrict__ gamma,
                                            const float* __restrict__ beta,
                                            float* __restrict__ out) {
    __shared__ float rs[2][8];
    int g = blockIdx.x, t = threadIdx.x;
    const float* src = g_proj + (size_t)g * 8 * N_;
    float sum = 0.f, sq = 0.f;
    for (int i = t; i < 8 * N_; i += 256) { float v = src[i]; sum += v; sq += v * v; }
#pragma unroll
    for (int o = 16; o; o >>= 1) {
        sum += __shfl_xor_sync(0xffffffffu, sum, o);
        sq  += __shfl_xor_sync(0xffffffffu, sq, o);
    }
    if ((t & 31) == 0) { rs[0][t >> 5] = sum; rs[1][t >> 5] = sq; }
    __syncthreads();
    if (t < 32) {
        float a = (t < 8) ? rs[0][t] : 0.f;
        float b = (t < 8) ? rs[1][t] : 0.f;
#pragma unroll
        for (int o = 4; o; o >>= 1) {
            a += __shfl_xor_sync(0xffffffffu, a, o);
            b += __shfl_xor_sync(0xffffffffu, b, o);
        }
        if (t == 0) { rs[0][0] = a; rs[1][0] = b; }
    }
    __syncthreads();
    float inv_m = 1.f / (8.f * N_);
    float mean = rs[0][0] * inv_m;
    float var = rs[1][0] * inv_m - mean * mean;
    float rstd = rsqrtf(var + 1e-6f);
    for (int i = t; i < 8 * N_; i += 256) {
        int c = g * 8 + (i >> 12);
        out[(size_t)g * 8 * N_ + i] = (src[i] - mean) * rstd * gamma[c] + beta[c];
    }
}

extern "C" void kernel_launch(void* const* d_in, const int* in_sizes, int n_in,
                              void* d_out, int out_size) {
    (void)in_sizes; (void)n_in; (void)out_size;
    const float* x      = (const float*)d_in[0];
    const float* w_qkv  = (const float*)d_in[1];
    const float* w_proj = (const float*)d_in[2];
    const float* gamma  = (const float*)d_in[3];
    const float* beta   = (const float*)d_in[4];
    float* out = (float*)d_out;

    cudaFuncSetAttribute(k_attn, cudaFuncAttributeMaxDynamicSharedMemorySize,
                         SM_TOT * (int)sizeof(float));

    // harness issues 2 internal launches first; ncu -s 5 captures global
    // index 5 = my index 3 -> k_attn.
    k_sgemm<<<dim3(32, 12), 256>>>(w_qkv, x, 0);               // my 0
    k_prep<<<dim3(128, 3), 256>>>();                            // my 1
    k_nop<<<1, 32>>>();                                         // my 2
    k_attn<<<dim3(512, 8), 512, SM_TOT * sizeof(float)>>>();    // my 3 (profiled)
    k_sgemm<<<dim3(32, 4), 256>>>(w_proj, nullptr, 1);          // my 4
    k_gn<<<32, 256>>>(gamma, beta, out);                        // my 5
}

// round 13
// speedup vs baseline: 2.0181x; 1.0393x over previous
#include <cuda_runtime.h>
#include <math.h>

#define N_ 4096
#define HD 32
#define KNUM 2048
#define SCALE 0.17677669529663687f

// scratch (__device__ globals: allocation-free rule)
__device__ float g_qkv[768 * N_];
__device__ float g_q[8 * N_ * HD];
__device__ float g_k[8 * N_ * HD];
__device__ float g_v[8 * N_ * HD];
__device__ float g_attn[256 * N_];
__device__ float g_proj[256 * N_];

// smem layout of k_attn (float offsets)
#define SC_OFF 0            // scores [8][4096]  (u-mapped uint in P1/P2, p after P3)
#define KT_OFF 32768        // tile   [512][36]
#define QS_OFF 51200        // qs     [8][32]
#define HI_OFF 51456        // hist   [8][256] (int)
#define PX_OFF 53504        // s_prefix [8] (uint)
#define WT_OFF 53512        // s_want   [8] (int)
#define PS_OFF 53520        // s_psum   [8][2]
#define RI_OFF 53536        // rowinv   [8]
#define SM_TOT 53544

// ---------------- SGEMM: C[M][4096] = A[M][256] * B[256][4096] ----------------
__global__ void __launch_bounds__(256) k_sgemm(const float* __restrict__ A,
                                               const float* __restrict__ Bx, int mode) {
    const float* B = mode ? (const float*)g_attn : Bx;
    float* C = mode ? g_proj : g_qkv;
    __shared__ float As[64][17];
    __shared__ float Bs[16][128];
    int t = threadIdx.x;
    int bm = blockIdx.y * 64, bn = blockIdx.x * 128;
    int tr = t >> 4, tc = t & 15;
    int arow = t >> 2, akk = (t & 3) * 4;
    int brow = t >> 4, bcol = (t & 15) * 8;
    float acc[4][8];
#pragma unroll
    for (int i = 0; i < 4; i++)
#pragma unroll
        for (int j = 0; j < 8; j++) acc[i][j] = 0.f;
    for (int k0 = 0; k0 < 256; k0 += 16) {
        float4 a4 = *(const float4*)&A[(bm + arow) * 256 + k0 + akk];
        float4 b0 = *(const float4*)&B[(size_t)(k0 + brow) * N_ + bn + bcol];
        float4 b1 = *(const float4*)&B[(size_t)(k0 + brow) * N_ + bn + bcol + 4];
        __syncthreads();
        As[arow][akk + 0] = a4.x; As[arow][akk + 1] = a4.y;
        As[arow][akk + 2] = a4.z; As[arow][akk + 3] = a4.w;
        *(float4*)&Bs[brow][bcol] = b0;
        *(float4*)&Bs[brow][bcol + 4] = b1;
        __syncthreads();
#pragma unroll
        for (int k = 0; k < 16; k++) {
            float4 bv0 = *(const float4*)&Bs[k][tc * 4];
            float4 bv1 = *(const float4*)&Bs[k][64 + tc * 4];
#pragma unroll
            for (int i = 0; i < 4; i++) {
                float a = As[tr * 4 + i][k];
                acc[i][0] += a * bv0.x; acc[i][1] += a * bv0.y;
                acc[i][2] += a * bv0.z; acc[i][3] += a * bv0.w;
                acc[i][4] += a * bv1.x; acc[i][5] += a * bv1.y;
                acc[i][6] += a * bv1.z; acc[i][7] += a * bv1.w;
            }
        }
    }
#pragma unroll
    for (int i = 0; i < 4; i++) {
        size_t row = bm + tr * 4 + i;
        *(float4*)&C[row * N_ + bn + tc * 4] =
            make_float4(acc[i][0], acc[i][1], acc[i][2], acc[i][3]);
        *(float4*)&C[row * N_ + bn + 64 + tc * 4] =
            make_float4(acc[i][4], acc[i][5], acc[i][6], acc[i][7]);
    }
}

// ---------- transpose [3C][N] -> [h][n][d] with l2norm for q,k ----------
__global__ void __launch_bounds__(256) k_prep() {
    int which = blockIdx.y;                         // 0=q 1=k 2=v
    int idx = blockIdx.x * 256 + threadIdx.x;       // h*4096+n
    int h = idx >> 12, n = idx & 4095;
    const float* src = g_qkv + (size_t)(which * 256 + h * 32) * N_ + n;
    float s[32], ss = 0.f;
#pragma unroll
    for (int d = 0; d < 32; d++) { s[d] = src[(size_t)d * N_]; ss += s[d] * s[d]; }
    float inv = 1.f;
    if (which < 2) inv = 1.f / fmaxf(sqrtf(ss), 1e-12f);
    float* dst = (which == 0 ? g_q : which == 1 ? g_k : g_v) + (size_t)idx * 32;
#pragma unroll
    for (int d = 0; d < 32; d++) dst[d] = s[d] * inv;
}

// no-op pad: keeps k_attn on ncu's skip-5 capture slot (harness pre-launches 2).
__global__ void k_nop() {}

// ---------------- fused attention: QK, radix topk, softmax, AV ----------------
// 512 threads (16 warps), 512-key tiles, coalesced tile loads.
// Balanced register blocking: warps 0-7 -> rows 0-3, warps 8-15 -> rows 4-7;
// each warp covers 64 keys x 4 rows per tile (lane = 4 rows x 2 keys in P1,
// 4-row dim-lane over 64 keys in P4). Scores stored u-mapped for radix select.
__global__ void __launch_bounds__(512) k_attn() {
    extern __shared__ float sm[];
    float*    scores  = sm + SC_OFF;            // [8][4096]
    float*    tile    = sm + KT_OFF;            // [512][36]
    float*    qs      = sm + QS_OFF;            // [8][32]
    int*      hist    = (int*)(sm + HI_OFF);    // [8][256]
    unsigned* sprefix = (unsigned*)(sm + PX_OFF);
    int*      swant   = (int*)(sm + WT_OFF);
    float*    psum    = sm + PS_OFF;            // [8][2]
    float*    rowinv  = sm + RI_OFF;            // [8]

    int h = blockIdx.y;
    int row0 = blockIdx.x * 8;
    int t = threadIdx.x, w = t >> 5, l = t & 31;
    const float* Q = g_q + (size_t)h * N_ * HD;
    const float* K = g_k + (size_t)h * N_ * HD;
    const float* V = g_v + (size_t)h * N_ * HD;

    // coalesced->scatter mapping for tile loads
    int st_key = t >> 3, st_dc = t & 7;
    // balanced blocking: row group + 64-key strip per warp
    int rgrp = w >> 3;               // 0: rows 0-3, 1: rows 4-7
    int kbase = (w & 7) * 64;        // 64-key strip

    if (t < 64) {   // 8 rows * 8 float4
        int r = t >> 3;
        ((float4*)qs)[t] = ((const float4*)(Q + (size_t)(row0 + r) * HD))[t & 7];
    }
    if (t < 8) { sprefix[t] = 0u; swant[t] = KNUM; }

    // ---- Phase 1: QK scores -> u-mapped uints in smem.
    {
        const float4* src = (const float4*)K;
        float4 pf[8];
#pragma unroll
        for (int i = 0; i < 8; i++) pf[i] = src[i * 512 + t];          // coalesced
        for (int tb = 0; tb < N_; tb += 512) {
            __syncthreads();
#pragma unroll
            for (int i = 0; i < 8; i++)
                *(float4*)&tile[(i * 64 + st_key) * 36 + st_dc * 4] = pf[i];
            __syncthreads();
            if (tb + 512 < N_) {
                const float4* nsrc = src + (size_t)(tb + 512) * 8;
#pragma unroll
                for (int i = 0; i < 8; i++) pf[i] = nsrc[i * 512 + t];
            }
            float acc[4][2];
#pragma unroll
            for (int i = 0; i < 4; i++) { acc[i][0] = 0.f; acc[i][1] = 0.f; }
#pragma unroll
            for (int dc = 0; dc < 8; dc++) {
                float4 kv0 = *(float4*)&tile[(kbase + l) * 36 + dc * 4];
                float4 kv1 = *(float4*)&tile[(kbase + 32 + l) * 36 + dc * 4];
#pragma unroll
                for (int i = 0; i < 4; i++) {
                    float4 qv = *(float4*)&qs[(rgrp * 4 + i) * 32 + dc * 4];
                    acc[i][0] += qv.x * kv0.x + qv.y * kv0.y + qv.z * kv0.z + qv.w * kv0.w;
                    acc[i][1] += qv.x * kv1.x + qv.y * kv1.y + qv.z * kv1.z + qv.w * kv1.w;
                }
            }
#pragma unroll
            for (int i = 0; i < 4; i++)
#pragma unroll
                for (int k2 = 0; k2 < 2; k2++) {
                    float s = fminf(fmaxf(acc[i][k2] * SCALE, -32.f), 32.f);
                    unsigned bb = __float_as_uint(s);
                    unsigned u = (bb & 0x80000000u) ? ~bb : (bb | 0x80000000u);
                    ((unsigned*)scores)[(rgrp * 4 + i) * N_ + tb + kbase + k2 * 32 + l] = u;
                }
        }
    }

    // ---- Phase 2: exact k-th largest per row, 4-pass radix select on u.
    // Row r scanned by warps 2r, 2r+1 (sub-lane 0..63), x4 batched loads.
    int r = w >> 1;
    int sub = (w & 1) * 32 + l;
    unsigned* urow = (unsigned*)scores + r * N_;
    for (int j = 3; j >= 0; j--) {
        for (int b = t; b < 2048; b += 512) ((int*)hist)[b] = 0;
        __syncthreads();
        unsigned prefix = sprefix[r];
        for (int i0 = sub; i0 < N_; i0 += 256) {
            unsigned uu[4];
#pragma unroll
            for (int q4 = 0; q4 < 4; q4++) uu[q4] = urow[i0 + q4 * 64];
#pragma unroll
            for (int q4 = 0; q4 < 4; q4++) {
                unsigned u = uu[q4];
                bool ok = (j == 3) || ((u >> ((j + 1) * 8)) == prefix);
                unsigned bin = ok ? ((u >> (j * 8)) & 255u) : 0xFFFFFFFFu;
                unsigned peers = __match_any_sync(0xffffffffu, bin);
                if (ok && (__ffs(peers) - 1 == l))
                    atomicAdd(&hist[r * 256 + bin], __popc(peers));
            }
        }
        __syncthreads();
        if ((w & 1) == 0) {           // warp 2r selects for row r, warp-parallel
            int want = swant[r];
            int base = 255 - l * 8;   // lane l owns 8 descending bins
            int cnt[8]; int local = 0;
#pragma unroll
            for (int i = 0; i < 8; i++) { cnt[i] = hist[r * 256 + base - i]; local += cnt[i]; }
            int pre = local;
#pragma unroll
            for (int o = 1; o < 32; o <<= 1) {
                int x = __shfl_up_sync(0xffffffffu, pre, o);
                if (l >= o) pre += x;
            }
            int cum_before = pre - local;
            if (cum_before < want && cum_before + local >= want) {
                int rem = want - cum_before;
                int c = 0;
#pragma unroll
                for (int i = 0; i < 8; i++) {
                    if (c + cnt[i] >= rem) {
                        sprefix[r] = (sprefix[r] << 8) | (unsigned)(base - i);
                        swant[r] = rem - c;
                        break;
                    }
                    c += cnt[i];
                }
            }
        }
        __syncthreads();
    }
    unsigned T = sprefix[r];          // uint key of exact k-th largest

    // ---- Phase 3: invert map, mask, exp, sum (|s|<=0.177: no max shift).
    {
        float sum = 0.f;
        for (int i0 = sub; i0 < N_; i0 += 256) {
            unsigned uu[4];
#pragma unroll
            for (int q4 = 0; q4 < 4; q4++) uu[q4] = urow[i0 + q4 * 64];
            float pp[4];
#pragma unroll
            for (int q4 = 0; q4 < 4; q4++) {
                unsigned u = uu[q4];
                unsigned bb = (u & 0x80000000u) ? (u & 0x7FFFFFFFu) : ~u;
                float s = __uint_as_float(bb);
                pp[q4] = (u >= T) ? __expf(s) : 0.f;
                sum += pp[q4];
            }
#pragma unroll
            for (int q4 = 0; q4 < 4; q4++)
                ((float*)urow)[i0 + q4 * 64] = pp[q4];
        }
#pragma unroll
        for (int o = 16; o; o >>= 1) sum += __shfl_xor_sync(0xffffffffu, sum, o);
        if (l == 0) psum[r * 2 + (w & 1)] = sum;
        __syncthreads();
        if (t < 8) rowinv[t] = 1.f / (psum[t * 2] + psum[t * 2 + 1]);
    }

    // ---- Phase 4: AV. Warp covers 64 keys x 4 rows per tile; lane = dim.
    float acc[4];
#pragma unroll
    for (int rr = 0; rr < 4; rr++) acc[rr] = 0.f;
    {
        const float4* src = (const float4*)V;
        float4 pf[8];
#pragma unroll
        for (int i = 0; i < 8; i++) pf[i] = src[i * 512 + t];          // coalesced
        for (int tb = 0; tb < N_; tb += 512) {
            __syncthreads();
#pragma unroll
            for (int i = 0; i < 8; i++)
                *(float4*)&tile[(i * 64 + st_key) * 36 + st_dc * 4] = pf[i];
            __syncthreads();
            if (tb + 512 < N_) {
                const float4* nsrc = src + (size_t)(tb + 512) * 8;
#pragma unroll
                for (int i = 0; i < 8; i++) pf[i] = nsrc[i * 512 + t];
            }
#pragma unroll
            for (int g = 0; g < 16; g++) {
                int n0 = kbase + g * 4;
                float4 p[4];
#pragma unroll
                for (int rr = 0; rr < 4; rr++)
                    p[rr] = *(float4*)&scores[(rgrp * 4 + rr) * N_ + tb + n0];
                float v0 = tile[(n0 + 0) * 36 + l];
                float v1 = tile[(n0 + 1) * 36 + l];
                float v2 = tile[(n0 + 2) * 36 + l];
                float v3 = tile[(n0 + 3) * 36 + l];
#pragma unroll
                for (int rr = 0; rr < 4; rr++)
                    acc[rr] += p[rr].x * v0 + p[rr].y * v1 + p[rr].z * v2 + p[rr].w * v3;
            }
        }
    }
    // cross-warp reduce: 8 warps per row-group (reuse tile buffer)
    __syncthreads();
    float* red = tile;
#pragma unroll
    for (int rr = 0; rr < 4; rr++) red[w * 128 + rr * 32 + l] = acc[rr];
    __syncthreads();
    if (t < 256) {
        int rr = t >> 5, d = t & 31;
        int wbase = (rr >> 2) * 8;        // rows 0-3 from warps 0-7; 4-7 from 8-15
        float o = 0.f;
#pragma unroll
        for (int ww = 0; ww < 8; ww++)
            o += red[(wbase + ww) * 128 + (rr & 3) * 32 + d];
        o *= rowinv[rr];
        g_attn[(size_t)(h * 32 + d) * N_ + row0 + rr] = o;
    }
}

// ---------------- GroupNorm(32 groups) ----------------
__global__ void __launch_bounds__(256) k_gn(const float* __restrict__ gamma,
                                            const float* __restrict__ beta,
                                            float* __restrict__ out) {
    __shared__ float rs[2][8];
    int g = blockIdx.x, t = threadIdx.x;
    const float* src = g_proj + (size_t)g * 8 * N_;
    float sum = 0.f, sq = 0.f;
    for (int i = t; i < 8 * N_; i += 256) { float v = src[i]; sum += v; sq += v * v; }
#pragma unroll
    for (int o = 16; o; o >>= 1) {
        sum += __shfl_xor_sync(0xffffffffu, sum, o);
        sq  += __shfl_xor_sync(0xffffffffu, sq, o);
    }
    if ((t & 31) == 0) { rs[0][t >> 5] = sum; rs[1][t >> 5] = sq; }
    __syncthreads();
    if (t < 32) {
        float a = (t < 8) ? rs[0][t] : 0.f;
        float b = (t < 8) ? rs[1][t] : 0.f;
#pragma unroll
        for (int o = 4; o; o >>= 1) {
            a += __shfl_xor_sync(0xffffffffu, a, o);
            b += __shfl_xor_sync(0xffffffffu, b, o);
        }
        if (t == 0) { rs[0][0] = a; rs[1][0] = b; }
    }
    __syncthreads();
    float inv_m = 1.f / (8.f * N_);
    float mean = rs[0][0] * inv_m;
    float var = rs[1][0] * inv_m - mean * mean;
    float rstd = rsqrtf(var + 1e-6f);
    for (int i = t; i < 8 * N_; i += 256) {
        int c = g * 8 + (i >> 12);
        out[(size_t)g * 8 * N_ + i] = (src[i] - mean) * rstd * gamma[c] + beta[c];
    }
}

extern "C" void kernel_launch(void* const* d_in, const int* in_sizes, int n_in,
                              void* d_out, int out_size) {
    (void)in_sizes; (void)n_in; (void)out_size;
    const float* x      = (const float*)d_in[0];
    const float* w_qkv  = (const float*)d_in[1];
    const float* w_proj = (const float*)d_in[2];
    const float* gamma  = (const float*)d_in[3];
    const float* beta   = (const float*)d_in[4];
    float* out = (float*)d_out;

    cudaFuncSetAttribute(k_attn, cudaFuncAttributeMaxDynamicSharedMemorySize,
                         SM_TOT * (int)sizeof(float));

    // harness issues 2 internal launches first; ncu -s 5 captures global
    // index 5 = my index 3 -> k_attn.
    k_sgemm<<<dim3(32, 12), 256>>>(w_qkv, x, 0);               // my 0
    k_prep<<<dim3(128, 3), 256>>>();                            // my 1
    k_nop<<<1, 32>>>();                                         // my 2
    k_attn<<<dim3(512, 8), 512, SM_TOT * sizeof(float)>>>();    // my 3 (profiled)
    k_sgemm<<<dim3(32, 4), 256>>>(w_proj, nullptr, 1);          // my 4
    k_gn<<<32, 256>>>(gamma, beta, out);                        // my 5
}

// round 14
// speedup vs baseline: 3.2387x; 1.6049x over previous
#include <cuda_runtime.h>
#include <math.h>

#define N_ 4096
#define HD 32
#define KNUM 2048
#define SCALE 0.17677669529663687f

// scratch (__device__ globals: allocation-free rule)
__device__ float    g_qkv[768 * N_];
__device__ float    g_q[8 * N_ * HD];              // [h][n][d]
__device__ float    g_kT[8 * HD * N_];             // [h][d][n]  (transposed K)
__device__ float    g_v[8 * N_ * HD];              // [h][n][d]
__device__ unsigned g_S[(size_t)8 * N_ * N_];      // u-mapped scores [h][row][key], 512MB
__device__ unsigned g_T[8 * N_];                   // per-row k-th threshold (u-mapped)
__device__ float    g_Inv[8 * N_];                 // per-row 1/sum(exp)
__device__ float    g_attn[256 * N_];
__device__ float    g_proj[256 * N_];

__device__ __forceinline__ unsigned umap_score(float a) {
    float s = fminf(fmaxf(a * SCALE, -32.f), 32.f);
    unsigned bb = __float_as_uint(s);
    return (bb & 0x80000000u) ? ~bb : (bb | 0x80000000u);
}

#define GETC(v4, kk) ((kk) == 0 ? (v4).x : (kk) == 1 ? (v4).y : (kk) == 2 ? (v4).z : (v4).w)

// ---------------- SGEMM: C[M][4096] = A[M][256] * B[256][4096] ----------------
__global__ void __launch_bounds__(256) k_sgemm(const float* __restrict__ A,
                                               const float* __restrict__ Bx, int mode) {
    const float* B = mode ? (const float*)g_attn : Bx;
    float* C = mode ? g_proj : g_qkv;
    __shared__ float As[64][17];
    __shared__ float Bs[16][128];
    int t = threadIdx.x;
    int bm = blockIdx.y * 64, bn = blockIdx.x * 128;
    int tr = t >> 4, tc = t & 15;
    int arow = t >> 2, akk = (t & 3) * 4;
    int brow = t >> 4, bcol = (t & 15) * 8;
    float acc[4][8];
#pragma unroll
    for (int i = 0; i < 4; i++)
#pragma unroll
        for (int j = 0; j < 8; j++) acc[i][j] = 0.f;
    for (int k0 = 0; k0 < 256; k0 += 16) {
        float4 a4 = *(const float4*)&A[(bm + arow) * 256 + k0 + akk];
        float4 b0 = *(const float4*)&B[(size_t)(k0 + brow) * N_ + bn + bcol];
        float4 b1 = *(const float4*)&B[(size_t)(k0 + brow) * N_ + bn + bcol + 4];
        __syncthreads();
        As[arow][akk + 0] = a4.x; As[arow][akk + 1] = a4.y;
        As[arow][akk + 2] = a4.z; As[arow][akk + 3] = a4.w;
        *(float4*)&Bs[brow][bcol] = b0;
        *(float4*)&Bs[brow][bcol + 4] = b1;
        __syncthreads();
#pragma unroll
        for (int k = 0; k < 16; k++) {
            float4 bv0 = *(const float4*)&Bs[k][tc * 4];
            float4 bv1 = *(const float4*)&Bs[k][64 + tc * 4];
#pragma unroll
            for (int i = 0; i < 4; i++) {
                float a = As[tr * 4 + i][k];
                acc[i][0] += a * bv0.x; acc[i][1] += a * bv0.y;
                acc[i][2] += a * bv0.z; acc[i][3] += a * bv0.w;
                acc[i][4] += a * bv1.x; acc[i][5] += a * bv1.y;
                acc[i][6] += a * bv1.z; acc[i][7] += a * bv1.w;
            }
        }
    }
#pragma unroll
    for (int i = 0; i < 4; i++) {
        size_t row = bm + tr * 4 + i;
        *(float4*)&C[row * N_ + bn + tc * 4] =
            make_float4(acc[i][0], acc[i][1], acc[i][2], acc[i][3]);
        *(float4*)&C[row * N_ + bn + 64 + tc * 4] =
            make_float4(acc[i][4], acc[i][5], acc[i][6], acc[i][7]);
    }
}

// ---- transpose [3C][N]: q -> [h][n][d] (l2norm), k -> [h][d][n] (l2norm), v -> [h][n][d]
__global__ void __launch_bounds__(256) k_prep() {
    int which = blockIdx.y;                         // 0=q 1=k 2=v
    int idx = blockIdx.x * 256 + threadIdx.x;       // h*4096+n
    int h = idx >> 12, n = idx & 4095;
    const float* src = g_qkv + (size_t)(which * 256 + h * 32) * N_ + n;
    float s[32], ss = 0.f;
#pragma unroll
    for (int d = 0; d < 32; d++) { s[d] = src[(size_t)d * N_]; ss += s[d] * s[d]; }
    float inv = 1.f;
    if (which < 2) inv = 1.f / fmaxf(sqrtf(ss), 1e-12f);
    if (which == 1) {           // K: store transposed [h][d][n]
#pragma unroll
        for (int d = 0; d < 32; d++)
            g_kT[(size_t)(h * 32 + d) * N_ + n] = s[d] * inv;
    } else {
        float* dst = (which == 0 ? g_q : g_v) + (size_t)idx * 32;
#pragma unroll
        for (int d = 0; d < 32; d++) dst[d] = s[d] * inv;
    }
}

// no-op pad: keeps k_qk on ncu's skip-5 capture slot (harness pre-launches 2).
__global__ void k_nop() {}

// ---------------- QK GEMM: S[h][row][key] = umap(clamp(q.k * scale)) ----------------
// 64 rows x 128 keys per CTA, Kdim=32 single load, 4x8 microtile.
// FMA grouping (a.x*b0 + a.y*b1 + a.z*b2 + a.w*b3 per 4-d chunk, chunks 0..7)
// reproduces the previous kernel's accumulation order exactly -> identical scores.
__global__ void __launch_bounds__(256) k_qk() {
    __shared__ float Qs[64 * 36];
    __shared__ float Ks[32 * 132];
    int t = threadIdx.x;
    int h = blockIdx.z;
    int i0 = blockIdx.y * 64;
    int j0 = blockIdx.x * 128;

    const float4* qsrc = (const float4*)(g_q + ((size_t)h * N_ + i0) * HD);
#pragma unroll
    for (int q = 0; q < 2; q++) {
        int idx = q * 256 + t;              // 0..511 float4s of 64x32 tile
        int row = idx >> 3, d4 = idx & 7;
        *(float4*)&Qs[row * 36 + d4 * 4] = qsrc[idx];
    }
#pragma unroll
    for (int q = 0; q < 4; q++) {
        int idx = q * 256 + t;              // 0..1023 float4s of 32x128 tile
        int d = idx >> 5, k4 = idx & 31;
        *(float4*)&Ks[d * 132 + k4 * 4] =
            *(const float4*)(g_kT + (size_t)(h * HD + d) * N_ + j0 + k4 * 4);
    }
    __syncthreads();

    int tr = t >> 4, tc = t & 15;
    float acc[4][8];
#pragma unroll
    for (int i = 0; i < 4; i++)
#pragma unroll
        for (int j = 0; j < 8; j++) acc[i][j] = 0.f;

#pragma unroll
    for (int dc = 0; dc < 8; dc++) {
        float4 b0[4], b1[4];
#pragma unroll
        for (int j = 0; j < 4; j++) {
            b0[j] = *(float4*)&Ks[(dc * 4 + j) * 132 + tc * 4];
            b1[j] = *(float4*)&Ks[(dc * 4 + j) * 132 + 64 + tc * 4];
        }
#pragma unroll
        for (int i = 0; i < 4; i++) {
            float4 a = *(float4*)&Qs[(tr * 4 + i) * 36 + dc * 4];
#pragma unroll
            for (int kk = 0; kk < 4; kk++) {
                acc[i][kk]     += a.x * GETC(b0[0], kk) + a.y * GETC(b0[1], kk)
                                + a.z * GETC(b0[2], kk) + a.w * GETC(b0[3], kk);
                acc[i][4 + kk] += a.x * GETC(b1[0], kk) + a.y * GETC(b1[1], kk)
                                + a.z * GETC(b1[2], kk) + a.w * GETC(b1[3], kk);
            }
        }
    }

#pragma unroll
    for (int i = 0; i < 4; i++) {
        int row = i0 + tr * 4 + i;
        size_t base = ((size_t)h * N_ + row) * N_ + j0;
        uint4 o0, o1;
        o0.x = umap_score(acc[i][0]); o0.y = umap_score(acc[i][1]);
        o0.z = umap_score(acc[i][2]); o0.w = umap_score(acc[i][3]);
        o1.x = umap_score(acc[i][4]); o1.y = umap_score(acc[i][5]);
        o1.z = umap_score(acc[i][6]); o1.w = umap_score(acc[i][7]);
        *(uint4*)&g_S[base + tc * 4] = o0;
        *(uint4*)&g_S[base + 64 + tc * 4] = o1;
    }
}

// ---------------- per-row select: exact k-th threshold + exp-sum ----------------
// One row per CTA (256 threads). Row in smem; 4-pass radix select; sum of exp.
__global__ void __launch_bounds__(256) k_sel() {
    __shared__ unsigned su[4096];
    __shared__ int hist[256];
    __shared__ unsigned s_pref;
    __shared__ int s_want;
    __shared__ float s_red[8];
    int b = blockIdx.x;                  // h*4096 + row
    int t = threadIdx.x, l = t & 31, w = t >> 5;

    const uint4* src = (const uint4*)(g_S + (size_t)b * N_);
#pragma unroll
    for (int q = 0; q < 4; q++)
        ((uint4*)su)[q * 256 + t] = src[q * 256 + t];
    if (t == 0) { s_pref = 0u; s_want = KNUM; }

    for (int j = 3; j >= 0; j--) {
        hist[t] = 0;
        __syncthreads();                 // publishes su (first pass) + s_pref/s_want
        unsigned prefix = s_pref;
#pragma unroll
        for (int q = 0; q < 4; q++) {
            unsigned uu[4];
#pragma unroll
            for (int x = 0; x < 4; x++) uu[x] = su[t + q * 1024 + x * 256];
#pragma unroll
            for (int x = 0; x < 4; x++) {
                unsigned u = uu[x];
                bool ok = (j == 3) || ((u >> ((j + 1) * 8)) == prefix);
                unsigned bin = ok ? ((u >> (j * 8)) & 255u) : 0xFFFFFFFFu;
                unsigned peers = __match_any_sync(0xffffffffu, bin);
                if (ok && (__ffs(peers) - 1 == l))
                    atomicAdd(&hist[bin], __popc(peers));
            }
        }
        __syncthreads();
        if (w == 0) {                    // warp-parallel suffix scan over 256 bins
            int want = s_want;
            int base = 255 - l * 8;
            int cnt[8]; int local = 0;
#pragma unroll
            for (int i = 0; i < 8; i++) { cnt[i] = hist[base - i]; local += cnt[i]; }
            int pre = local;
#pragma unroll
            for (int o = 1; o < 32; o <<= 1) {
                int x = __shfl_up_sync(0xffffffffu, pre, o);
                if (l >= o) pre += x;
            }
            int cum_before = pre - local;
            if (cum_before < want && cum_before + local >= want) {
                int rem = want - cum_before;
                int c = 0;
#pragma unroll
                for (int i = 0; i < 8; i++) {
                    if (c + cnt[i] >= rem) {
                        s_pref = (s_pref << 8) | (unsigned)(base - i);
                        s_want = rem - c;
                        break;
                    }
                    c += cnt[i];
                }
            }
        }
        __syncthreads();
    }
    unsigned T = s_pref;

    float sum = 0.f;
    for (int i = t; i < N_; i += 256) {
        unsigned u = su[i];
        if (u >= T) {
            unsigned bb = (u & 0x80000000u) ? (u & 0x7FFFFFFFu) : ~u;
            sum += __expf(__uint_as_float(bb));
        }
    }
#pragma unroll
    for (int o = 16; o; o >>= 1) sum += __shfl_xor_sync(0xffffffffu, sum, o);
    if (l == 0) s_red[w] = sum;
    __syncthreads();
    if (t == 0) {
        float tot = 0.f;
#pragma unroll
        for (int i = 0; i < 8; i++) tot += s_red[i];
        g_T[b] = T;
        g_Inv[b] = 1.f / tot;
    }
}

// ---------------- AV GEMM: out = softmax(P) * V ----------------
// 128 rows x 32 dims per CTA; K-chunks of 128 keys; S decoded to P smem on the fly.
#define AVP_OFF 0                        // P [128][132]
#define AVV_OFF (128 * 132)              // V [128][36]
#define AVT_OFF (AVV_OFF + 128 * 36)     // T [128] (uint)
#define AVI_OFF (AVT_OFF + 128)          // Inv [128]
#define AV_TOT  (AVI_OFF + 128)          // 21760 floats = 87040 bytes

__global__ void __launch_bounds__(256, 2) k_av() {
    extern __shared__ float avs[];
    float*    P    = avs + AVP_OFF;
    float*    V    = avs + AVV_OFF;
    unsigned* sT   = (unsigned*)(avs + AVT_OFF);
    float*    sInv = avs + AVI_OFF;

    int t = threadIdx.x;
    int h = blockIdx.y;
    int r0 = blockIdx.x * 128;
    int rg = t >> 3, dg = t & 7;         // 32 rowgroups x 8 dimgroups

    if (t < 128) {
        sT[t]   = g_T[h * N_ + r0 + t];
        sInv[t] = g_Inv[h * N_ + r0 + t];
    }

    float acc[4][4];
#pragma unroll
    for (int i = 0; i < 4; i++)
#pragma unroll
        for (int d = 0; d < 4; d++) acc[i][d] = 0.f;

    const unsigned* Sbase = g_S + ((size_t)h * N_ + r0) * N_;
    const float4* Vsrc = (const float4*)(g_v + (size_t)h * N_ * HD);

    for (int m0 = 0; m0 < N_; m0 += 128) {
        __syncthreads();
        // decode S chunk -> P smem (128 rows x 128 keys)
#pragma unroll
        for (int q = 0; q < 16; q++) {
            int idx = q * 256 + t;
            int row = idx >> 5, k4 = idx & 31;
            uint4 u4 = *(const uint4*)&Sbase[(size_t)row * N_ + m0 + k4 * 4];
            unsigned Tr = sT[row];
            float4 p4;
            {
                unsigned u = u4.x; float p = 0.f;
                if (u >= Tr) { unsigned bb = (u & 0x80000000u) ? (u & 0x7FFFFFFFu) : ~u;
                               p = __expf(__uint_as_float(bb)); }
                p4.x = p;
            }
            {
                unsigned u = u4.y; float p = 0.f;
                if (u >= Tr) { unsigned bb = (u & 0x80000000u) ? (u & 0x7FFFFFFFu) : ~u;
                               p = __expf(__uint_as_float(bb)); }
                p4.y = p;
            }
            {
                unsigned u = u4.z; float p = 0.f;
                if (u >= Tr) { unsigned bb = (u & 0x80000000u) ? (u & 0x7FFFFFFFu) : ~u;
                               p = __expf(__uint_as_float(bb)); }
                p4.z = p;
            }
            {
                unsigned u = u4.w; float p = 0.f;
                if (u >= Tr) { unsigned bb = (u & 0x80000000u) ? (u & 0x7FFFFFFFu) : ~u;
                               p = __expf(__uint_as_float(bb)); }
                p4.w = p;
            }
            *(float4*)&P[row * 132 + k4 * 4] = p4;
        }
        // V chunk (128 keys x 32 dims)
#pragma unroll
        for (int q = 0; q < 4; q++) {
            int idx = q * 256 + t;
            int key = idx >> 3, d4 = idx & 7;
            *(float4*)&V[key * 36 + d4 * 4] = Vsrc[(size_t)(m0 + key) * 8 + d4];
        }
        __syncthreads();
        // compute: 4 rows x 4 dims per thread over 128 keys
        for (int m = 0; m < 128; m += 4) {
            float4 v0 = *(float4*)&V[(m + 0) * 36 + dg * 4];
            float4 v1 = *(float4*)&V[(m + 1) * 36 + dg * 4];
            float4 v2 = *(float4*)&V[(m + 2) * 36 + dg * 4];
            float4 v3 = *(float4*)&V[(m + 3) * 36 + dg * 4];
#pragma unroll
            for (int i = 0; i < 4; i++) {
                float4 p = *(float4*)&P[(rg * 4 + i) * 132 + m];
                acc[i][0] += p.x * v0.x + p.y * v1.x + p.z * v2.x + p.w * v3.x;
                acc[i][1] += p.x * v0.y + p.y * v1.y + p.z * v2.y + p.w * v3.y;
                acc[i][2] += p.x * v0.z + p.y * v1.z + p.z * v2.z + p.w * v3.z;
                acc[i][3] += p.x * v0.w + p.y * v1.w + p.z * v2.w + p.w * v3.w;
            }
        }
    }

#pragma unroll
    for (int i = 0; i < 4; i++) {
        int row = r0 + rg * 4 + i;
        float inv = sInv[rg * 4 + i];
#pragma unroll
        for (int dd = 0; dd < 4; dd++)
            g_attn[(size_t)(h * 32 + dg * 4 + dd) * N_ + row] = acc[i][dd] * inv;
    }
}

// ---------------- GroupNorm(32 groups) ----------------
__global__ void __launch_bounds__(256) k_gn(const float* __restrict__ gamma,
                                            const float* __restrict__ beta,
                                            float* __restrict__ out) {
    __shared__ float rs[2][8];
    int g = blockIdx.x, t = threadIdx.x;
    const float* src = g_proj + (size_t)g * 8 * N_;
    float sum = 0.f, sq = 0.f;
    for (int i = t; i < 8 * N_; i += 256) { float v = src[i]; sum += v; sq += v * v; }
#pragma unroll
    for (int o = 16; o; o >>= 1) {
        sum += __shfl_xor_sync(0xffffffffu, sum, o);
        sq  += __shfl_xor_sync(0xffffffffu, sq, o);
    }
    if ((t & 31) == 0) { rs[0][t >> 5] = sum; rs[1][t >> 5] = sq; }
    __syncthreads();
    if (t < 32) {
        float a = (t < 8) ? rs[0][t] : 0.f;
        float b = (t < 8) ? rs[1][t] : 0.f;
#pragma unroll
        for (int o = 4; o; o >>= 1) {
            a += __shfl_xor_sync(0xffffffffu, a, o);
            b += __shfl_xor_sync(0xffffffffu, b, o);
        }
        if (t == 0) { rs[0][0] = a; rs[1][0] = b; }
    }
    __syncthreads();
    float inv_m = 1.f / (8.f * N_);
    float mean = rs[0][0] * inv_m;
    float var = rs[1][0] * inv_m - mean * mean;
    float rstd = rsqrtf(var + 1e-6f);
    for (int i = t; i < 8 * N_; i += 256) {
        int c = g * 8 + (i >> 12);
        out[(size_t)g * 8 * N_ + i] = (src[i] - mean) * rstd * gamma[c] + beta[c];
    }
}

extern "C" void kernel_launch(void* const* d_in, const int* in_sizes, int n_in,
                              void* d_out, int out_size) {
    (void)in_sizes; (void)n_in; (void)out_size;
    const float* x      = (const float*)d_in[0];
    const float* w_qkv  = (const float*)d_in[1];
    const float* w_proj = (const float*)d_in[2];
    const float* gamma  = (const float*)d_in[3];
    const float* beta   = (const float*)d_in[4];
    float* out = (float*)d_out;

    cudaFuncSetAttribute(k_av, cudaFuncAttributeMaxDynamicSharedMemorySize,
                         AV_TOT * (int)sizeof(float));

    // harness issues 2 internal launches first; ncu -s 5 captures global
    // index 5 = my index 3 -> k_qk.
    k_sgemm<<<dim3(32, 12), 256>>>(w_qkv, x, 0);               // my 0: qkv
    k_prep<<<dim3(128, 3), 256>>>();                            // my 1
    k_nop<<<1, 32>>>();                                         // my 2
    k_qk<<<dim3(32, 64, 8), 256>>>();                           // my 3 (profiled)
    k_sel<<<32768, 256>>>();                                    // my 4
    k_av<<<dim3(32, 8), 256, AV_TOT * sizeof(float)>>>();       // my 5
    k_sgemm<<<dim3(32, 4), 256>>>(w_proj, nullptr, 1);          // my 6: proj
    k_gn<<<32, 256>>>(gamma, beta, out);                        // my 7
}

// round 15
// speedup vs baseline: 3.2538x; 1.0047x over previous
#include <cuda_runtime.h>
#include <math.h>

#define N_ 4096
#define HD 32
#define KNUM 2048
#define SCALE 0.17677669529663687f

// scratch (__device__ globals: allocation-free rule)
__device__ float    g_qkv[768 * N_];
__device__ float    g_q[8 * N_ * HD];              // [h][n][d]
__device__ float    g_kT[8 * HD * N_];             // [h][d][n]  (transposed K)
__device__ float    g_v[8 * N_ * HD];              // [h][n][d]
__device__ unsigned g_S[(size_t)8 * N_ * N_];      // u-mapped scores [h][row][key], 512MB
__device__ unsigned g_T[8 * N_];                   // per-row k-th threshold (u-mapped)
__device__ float    g_Inv[8 * N_];                 // per-row 1/sum(exp)
__device__ float    g_attn[256 * N_];
__device__ float    g_proj[256 * N_];

__device__ __forceinline__ unsigned umap_score(float a) {
    float s = fminf(fmaxf(a * SCALE, -32.f), 32.f);
    unsigned bb = __float_as_uint(s);
    return (bb & 0x80000000u) ? ~bb : (bb | 0x80000000u);
}

__device__ __forceinline__ float udecode_p(unsigned u, unsigned T) {
    if (u < T) return 0.f;
    unsigned bb = (u & 0x80000000u) ? (u & 0x7FFFFFFFu) : ~u;
    return __expf(__uint_as_float(bb));
}

#define GETC(v4, kk) ((kk) == 0 ? (v4).x : (kk) == 1 ? (v4).y : (kk) == 2 ? (v4).z : (v4).w)

// ---------------- SGEMM: C[M][4096] = A[M][256] * B[256][4096] ----------------
__global__ void __launch_bounds__(256) k_sgemm(const float* __restrict__ A,
                                               const float* __restrict__ Bx, int mode) {
    const float* B = mode ? (const float*)g_attn : Bx;
    float* C = mode ? g_proj : g_qkv;
    __shared__ float As[64][17];
    __shared__ float Bs[16][128];
    int t = threadIdx.x;
    int bm = blockIdx.y * 64, bn = blockIdx.x * 128;
    int tr = t >> 4, tc = t & 15;
    int arow = t >> 2, akk = (t & 3) * 4;
    int brow = t >> 4, bcol = (t & 15) * 8;
    float acc[4][8];
#pragma unroll
    for (int i = 0; i < 4; i++)
#pragma unroll
        for (int j = 0; j < 8; j++) acc[i][j] = 0.f;
    for (int k0 = 0; k0 < 256; k0 += 16) {
        float4 a4 = *(const float4*)&A[(bm + arow) * 256 + k0 + akk];
        float4 b0 = *(const float4*)&B[(size_t)(k0 + brow) * N_ + bn + bcol];
        float4 b1 = *(const float4*)&B[(size_t)(k0 + brow) * N_ + bn + bcol + 4];
        __syncthreads();
        As[arow][akk + 0] = a4.x; As[arow][akk + 1] = a4.y;
        As[arow][akk + 2] = a4.z; As[arow][akk + 3] = a4.w;
        *(float4*)&Bs[brow][bcol] = b0;
        *(float4*)&Bs[brow][bcol + 4] = b1;
        __syncthreads();
#pragma unroll
        for (int k = 0; k < 16; k++) {
            float4 bv0 = *(const float4*)&Bs[k][tc * 4];
            float4 bv1 = *(const float4*)&Bs[k][64 + tc * 4];
#pragma unroll
            for (int i = 0; i < 4; i++) {
                float a = As[tr * 4 + i][k];
                acc[i][0] += a * bv0.x; acc[i][1] += a * bv0.y;
                acc[i][2] += a * bv0.z; acc[i][3] += a * bv0.w;
                acc[i][4] += a * bv1.x; acc[i][5] += a * bv1.y;
                acc[i][6] += a * bv1.z; acc[i][7] += a * bv1.w;
            }
        }
    }
#pragma unroll
    for (int i = 0; i < 4; i++) {
        size_t row = bm + tr * 4 + i;
        *(float4*)&C[row * N_ + bn + tc * 4] =
            make_float4(acc[i][0], acc[i][1], acc[i][2], acc[i][3]);
        *(float4*)&C[row * N_ + bn + 64 + tc * 4] =
            make_float4(acc[i][4], acc[i][5], acc[i][6], acc[i][7]);
    }
}

// ---- transpose [3C][N]: q -> [h][n][d] (l2norm), k -> [h][d][n] (l2norm), v -> [h][n][d]
__global__ void __launch_bounds__(256) k_prep() {
    int which = blockIdx.y;                         // 0=q 1=k 2=v
    int idx = blockIdx.x * 256 + threadIdx.x;       // h*4096+n
    int h = idx >> 12, n = idx & 4095;
    const float* src = g_qkv + (size_t)(which * 256 + h * 32) * N_ + n;
    float s[32], ss = 0.f;
#pragma unroll
    for (int d = 0; d < 32; d++) { s[d] = src[(size_t)d * N_]; ss += s[d] * s[d]; }
    float inv = 1.f;
    if (which < 2) inv = 1.f / fmaxf(sqrtf(ss), 1e-12f);
    if (which == 1) {           // K: store transposed [h][d][n]
#pragma unroll
        for (int d = 0; d < 32; d++)
            g_kT[(size_t)(h * 32 + d) * N_ + n] = s[d] * inv;
    } else {
        float* dst = (which == 0 ? g_q : g_v) + (size_t)idx * 32;
#pragma unroll
        for (int d = 0; d < 32; d++) dst[d] = s[d] * inv;
    }
}

// ---------------- QK GEMM: S[h][row][key] = umap(clamp(q.k * scale)) ----------------
// 64 rows x 128 keys per CTA, Kdim=32 single load, 4x8 microtile.
// FMA grouping reproduces prior accumulation order exactly -> identical scores.
__global__ void __launch_bounds__(256) k_qk() {
    __shared__ float Qs[64 * 36];
    __shared__ float Ks[32 * 132];
    int t = threadIdx.x;
    int h = blockIdx.z;
    int i0 = blockIdx.y * 64;
    int j0 = blockIdx.x * 128;

    const float4* qsrc = (const float4*)(g_q + ((size_t)h * N_ + i0) * HD);
#pragma unroll
    for (int q = 0; q < 2; q++) {
        int idx = q * 256 + t;
        int row = idx >> 3, d4 = idx & 7;
        *(float4*)&Qs[row * 36 + d4 * 4] = qsrc[idx];
    }
#pragma unroll
    for (int q = 0; q < 4; q++) {
        int idx = q * 256 + t;
        int d = idx >> 5, k4 = idx & 31;
        *(float4*)&Ks[d * 132 + k4 * 4] =
            *(const float4*)(g_kT + (size_t)(h * HD + d) * N_ + j0 + k4 * 4);
    }
    __syncthreads();

    int tr = t >> 4, tc = t & 15;
    float acc[4][8];
#pragma unroll
    for (int i = 0; i < 4; i++)
#pragma unroll
        for (int j = 0; j < 8; j++) acc[i][j] = 0.f;

#pragma unroll
    for (int dc = 0; dc < 8; dc++) {
        float4 b0[4], b1[4];
#pragma unroll
        for (int j = 0; j < 4; j++) {
            b0[j] = *(float4*)&Ks[(dc * 4 + j) * 132 + tc * 4];
            b1[j] = *(float4*)&Ks[(dc * 4 + j) * 132 + 64 + tc * 4];
        }
#pragma unroll
        for (int i = 0; i < 4; i++) {
            float4 a = *(float4*)&Qs[(tr * 4 + i) * 36 + dc * 4];
#pragma unroll
            for (int kk = 0; kk < 4; kk++) {
                acc[i][kk]     += a.x * GETC(b0[0], kk) + a.y * GETC(b0[1], kk)
                                + a.z * GETC(b0[2], kk) + a.w * GETC(b0[3], kk);
                acc[i][4 + kk] += a.x * GETC(b1[0], kk) + a.y * GETC(b1[1], kk)
                                + a.z * GETC(b1[2], kk) + a.w * GETC(b1[3], kk);
            }
        }
    }

#pragma unroll
    for (int i = 0; i < 4; i++) {
        int row = i0 + tr * 4 + i;
        size_t base = ((size_t)h * N_ + row) * N_ + j0;
        uint4 o0, o1;
        o0.x = umap_score(acc[i][0]); o0.y = umap_score(acc[i][1]);
        o0.z = umap_score(acc[i][2]); o0.w = umap_score(acc[i][3]);
        o1.x = umap_score(acc[i][4]); o1.y = umap_score(acc[i][5]);
        o1.z = umap_score(acc[i][6]); o1.w = umap_score(acc[i][7]);
        *(uint4*)&g_S[base + tc * 4] = o0;
        *(uint4*)&g_S[base + 64 + tc * 4] = o1;
    }
}

// ---------------- per-row select: exact k-th threshold + exp-sum ----------------
// One row per CTA (256 threads). Row in smem; 4-pass radix select; sum of exp.
__global__ void __launch_bounds__(256) k_sel() {
    __shared__ unsigned su[4096];
    __shared__ int hist[256];
    __shared__ unsigned s_pref;
    __shared__ int s_want;
    __shared__ float s_red[8];
    int b = blockIdx.x;                  // h*4096 + row
    int t = threadIdx.x, l = t & 31, w = t >> 5;

    const uint4* src = (const uint4*)(g_S + (size_t)b * N_);
#pragma unroll
    for (int q = 0; q < 4; q++)
        ((uint4*)su)[q * 256 + t] = src[q * 256 + t];
    if (t == 0) { s_pref = 0u; s_want = KNUM; }

    for (int j = 3; j >= 0; j--) {
        hist[t] = 0;
        __syncthreads();
        unsigned prefix = s_pref;
#pragma unroll
        for (int q = 0; q < 4; q++) {
            unsigned uu[4];
#pragma unroll
            for (int x = 0; x < 4; x++) uu[x] = su[t + q * 1024 + x * 256];
#pragma unroll
            for (int x = 0; x < 4; x++) {
                unsigned u = uu[x];
                bool ok = (j == 3) || ((u >> ((j + 1) * 8)) == prefix);
                unsigned bin = ok ? ((u >> (j * 8)) & 255u) : 0xFFFFFFFFu;
                unsigned peers = __match_any_sync(0xffffffffu, bin);
                if (ok && (__ffs(peers) - 1 == l))
                    atomicAdd(&hist[bin], __popc(peers));
            }
        }
        __syncthreads();
        if (w == 0) {
            int want = s_want;
            int base = 255 - l * 8;
            int cnt[8]; int local = 0;
#pragma unroll
            for (int i = 0; i < 8; i++) { cnt[i] = hist[base - i]; local += cnt[i]; }
            int pre = local;
#pragma unroll
            for (int o = 1; o < 32; o <<= 1) {
                int x = __shfl_up_sync(0xffffffffu, pre, o);
                if (l >= o) pre += x;
            }
            int cum_before = pre - local;
            if (cum_before < want && cum_before + local >= want) {
                int rem = want - cum_before;
                int c = 0;
#pragma unroll
                for (int i = 0; i < 8; i++) {
                    if (c + cnt[i] >= rem) {
                        s_pref = (s_pref << 8) | (unsigned)(base - i);
                        s_want = rem - c;
                        break;
                    }
                    c += cnt[i];
                }
            }
        }
        __syncthreads();
    }
    unsigned T = s_pref;

    float sum = 0.f;
    for (int i = t; i < N_; i += 256) {
        unsigned u = su[i];
        if (u >= T) {
            unsigned bb = (u & 0x80000000u) ? (u & 0x7FFFFFFFu) : ~u;
            sum += __expf(__uint_as_float(bb));
        }
    }
#pragma unroll
    for (int o = 16; o; o >>= 1) sum += __shfl_xor_sync(0xffffffffu, sum, o);
    if (l == 0) s_red[w] = sum;
    __syncthreads();
    if (t == 0) {
        float tot = 0.f;
#pragma unroll
        for (int i = 0; i < 8; i++) tot += s_red[i];
        g_T[b] = T;
        g_Inv[b] = 1.f / tot;
    }
}

// ---------------- AV GEMM: out = softmax(P) * V ----------------
// 128 rows x 32 dims per CTA; 128-key chunks; 2-way key split; 8 rows x 4 dims
// per thread (consecutive-row warp layout -> conflict-free P, 1-wf V reads).
#define AVP_OFF 0                        // P [128][132]
#define AVV_OFF (128 * 132)              // V [128][36]
#define AVT_OFF (AVV_OFF + 128 * 36)     // T [128] (uint)
#define AVI_OFF (AVT_OFF + 128)          // Inv [128]
#define AV_TOT  (AVI_OFF + 128)          // 21760 floats = 87040 bytes

__global__ void __launch_bounds__(256, 2) k_av() {
    extern __shared__ float avs[];
    float*    P    = avs + AVP_OFF;
    float*    V    = avs + AVV_OFF;
    unsigned* sT   = (unsigned*)(avs + AVT_OFF);
    float*    sInv = avs + AVI_OFF;

    int t = threadIdx.x;
    int h = blockIdx.y;
    int r0 = blockIdx.x * 128;
    int ks = t >> 7;                     // key half (0/1)
    int u7 = t & 127;
    int w4 = u7 >> 5;                    // warp-within-half: rows [w4*32, w4*32+32)
    int lane = u7 & 31;
    int row_lo = lane & 3;               // consecutive rows in warp -> no bank conflict
    int dg = lane >> 2;                  // 8 dim groups x 4 dims

    if (t < 128) {
        sT[t]   = g_T[h * N_ + r0 + t];
        sInv[t] = g_Inv[h * N_ + r0 + t];
    }

    float acc[8][4];
#pragma unroll
    for (int i = 0; i < 8; i++)
#pragma unroll
        for (int d = 0; d < 4; d++) acc[i][d] = 0.f;

    const unsigned* Sbase = g_S + ((size_t)h * N_ + r0) * N_;
    const float4* Vsrc = (const float4*)(g_v + (size_t)h * N_ * HD);

    for (int m0 = 0; m0 < N_; m0 += 128) {
        __syncthreads();
        // decode S chunk -> P smem (128 rows x 128 keys), coalesced per warp
#pragma unroll
        for (int q = 0; q < 16; q++) {
            int idx = q * 256 + t;
            int row = idx >> 5, k4 = idx & 31;
            uint4 u4 = *(const uint4*)&Sbase[(size_t)row * N_ + m0 + k4 * 4];
            unsigned Tr = sT[row];
            float4 p4;
            p4.x = udecode_p(u4.x, Tr);
            p4.y = udecode_p(u4.y, Tr);
            p4.z = udecode_p(u4.z, Tr);
            p4.w = udecode_p(u4.w, Tr);
            *(float4*)&P[row * 132 + k4 * 4] = p4;
        }
        // V chunk (128 keys x 32 dims)
#pragma unroll
        for (int q = 0; q < 4; q++) {
            int idx = q * 256 + t;
            int key = idx >> 3, d4 = idx & 7;
            *(float4*)&V[key * 36 + d4 * 4] = Vsrc[(size_t)(m0 + key) * 8 + d4];
        }
        __syncthreads();
        // compute: own 64-key half; 8 rows x 4 dims per thread
        int kb = ks * 64;
        for (int m = 0; m < 64; m += 4) {
            float4 v0 = *(float4*)&V[(kb + m + 0) * 36 + dg * 4];
            float4 v1 = *(float4*)&V[(kb + m + 1) * 36 + dg * 4];
            float4 v2 = *(float4*)&V[(kb + m + 2) * 36 + dg * 4];
            float4 v3 = *(float4*)&V[(kb + m + 3) * 36 + dg * 4];
#pragma unroll
            for (int i = 0; i < 8; i++) {
                int R = w4 * 32 + row_lo + 4 * i;
                float4 p = *(float4*)&P[R * 132 + kb + m];
                acc[i][0] += p.x * v0.x + p.y * v1.x + p.z * v2.x + p.w * v3.x;
                acc[i][1] += p.x * v0.y + p.y * v1.y + p.z * v2.y + p.w * v3.y;
                acc[i][2] += p.x * v0.z + p.y * v1.z + p.z * v2.z + p.w * v3.z;
                acc[i][3] += p.x * v0.w + p.y * v1.w + p.z * v2.w + p.w * v3.w;
            }
        }
    }

    // reduce the two key halves via smem (reuse P buffer; stride 36 conflict-free)
    __syncthreads();
    float* red = avs;                    // 128 x 36
    if (ks == 1) {
#pragma unroll
        for (int i = 0; i < 8; i++) {
            int R = w4 * 32 + row_lo + 4 * i;
            *(float4*)&red[R * 36 + dg * 4] =
                make_float4(acc[i][0], acc[i][1], acc[i][2], acc[i][3]);
        }
    }
    __syncthreads();
    if (ks == 0) {
#pragma unroll
        for (int i = 0; i < 8; i++) {
            int R = w4 * 32 + row_lo + 4 * i;
            float4 o = *(float4*)&red[R * 36 + dg * 4];
            float inv = sInv[R];
            int row = r0 + R;
            g_attn[(size_t)(h * 32 + dg * 4 + 0) * N_ + row] = (acc[i][0] + o.x) * inv;
            g_attn[(size_t)(h * 32 + dg * 4 + 1) * N_ + row] = (acc[i][1] + o.y) * inv;
            g_attn[(size_t)(h * 32 + dg * 4 + 2) * N_ + row] = (acc[i][2] + o.z) * inv;
            g_attn[(size_t)(h * 32 + dg * 4 + 3) * N_ + row] = (acc[i][3] + o.w) * inv;
        }
    }
}

// ---------------- GroupNorm(32 groups) ----------------
__global__ void __launch_bounds__(256) k_gn(const float* __restrict__ gamma,
                                            const float* __restrict__ beta,
                                            float* __restrict__ out) {
    __shared__ float rs[2][8];
    int g = blockIdx.x, t = threadIdx.x;
    const float* src = g_proj + (size_t)g * 8 * N_;
    float sum = 0.f, sq = 0.f;
    for (int i = t; i < 8 * N_; i += 256) { float v = src[i]; sum += v; sq += v * v; }
#pragma unroll
    for (int o = 16; o; o >>= 1) {
        sum += __shfl_xor_sync(0xffffffffu, sum, o);
        sq  += __shfl_xor_sync(0xffffffffu, sq, o);
    }
    if ((t & 31) == 0) { rs[0][t >> 5] = sum; rs[1][t >> 5] = sq; }
    __syncthreads();
    if (t < 32) {
        float a = (t < 8) ? rs[0][t] : 0.f;
        float b = (t < 8) ? rs[1][t] : 0.f;
#pragma unroll
        for (int o = 4; o; o >>= 1) {
            a += __shfl_xor_sync(0xffffffffu, a, o);
            b += __shfl_xor_sync(0xffffffffu, b, o);
        }
        if (t == 0) { rs[0][0] = a; rs[1][0] = b; }
    }
    __syncthreads();
    float inv_m = 1.f / (8.f * N_);
    float mean = rs[0][0] * inv_m;
    float var = rs[1][0] * inv_m - mean * mean;
    float rstd = rsqrtf(var + 1e-6f);
    for (int i = t; i < 8 * N_; i += 256) {
        int c = g * 8 + (i >> 12);
        out[(size_t)g * 8 * N_ + i] = (src[i] - mean) * rstd * gamma[c] + beta[c];
    }
}

extern "C" void kernel_launch(void* const* d_in, const int* in_sizes, int n_in,
                              void* d_out, int out_size) {
    (void)in_sizes; (void)n_in; (void)out_size;
    const float* x      = (const float*)d_in[0];
    const float* w_qkv  = (const float*)d_in[1];
    const float* w_proj = (const float*)d_in[2];
    const float* gamma  = (const float*)d_in[3];
    const float* beta   = (const float*)d_in[4];
    float* out = (float*)d_out;

    cudaFuncSetAttribute(k_av, cudaFuncAttributeMaxDynamicSharedMemorySize,
                         AV_TOT * (int)sizeof(float));

    // harness issues 2 internal launches first; ncu -s 5 captures global
    // index 5 = my index 3 -> k_sel this round.
    k_sgemm<<<dim3(32, 12), 256>>>(w_qkv, x, 0);               // my 0: qkv
    k_prep<<<dim3(128, 3), 256>>>();                            // my 1
    k_qk<<<dim3(32, 64, 8), 256>>>();                           // my 2
    k_sel<<<32768, 256>>>();                                    // my 3 (profiled)
    k_av<<<dim3(32, 8), 256, AV_TOT * sizeof(float)>>>();       // my 4
    k_sgemm<<<dim3(32, 4), 256>>>(w_proj, nullptr, 1);          // my 5: proj
    k_gn<<<32, 256>>>(gamma, beta, out);                        // my 6
}

// round 16
// speedup vs baseline: 3.7933x; 1.1658x over previous
#include <cuda_runtime.h>
#include <math.h>

#define N_ 4096
#define HD 32
#define KNUM 2048
#define SCALE 0.17677669529663687f

// scratch (__device__ globals: allocation-free rule)
__device__ float    g_qkv[768 * N_];
__device__ float    g_q[8 * N_ * HD];              // [h][n][d]
__device__ float    g_kT[8 * HD * N_];             // [h][d][n]  (transposed K)
__device__ float    g_v[8 * N_ * HD];              // [h][n][d]
__device__ unsigned g_S[(size_t)8 * N_ * N_];      // u-mapped scores [h][row][key], 512MB
__device__ unsigned g_T[8 * N_];                   // per-row k-th threshold (u-mapped)
__device__ float    g_Inv[8 * N_];                 // per-row 1/sum(exp)
__device__ float    g_attn[256 * N_];
__device__ float    g_proj[256 * N_];

__device__ __forceinline__ unsigned umap_score(float a) {
    float s = fminf(fmaxf(a * SCALE, -32.f), 32.f);
    unsigned bb = __float_as_uint(s);
    return (bb & 0x80000000u) ? ~bb : (bb | 0x80000000u);
}

__device__ __forceinline__ float udecode_p(unsigned u, unsigned T) {
    if (u < T) return 0.f;
    unsigned bb = (u & 0x80000000u) ? (u & 0x7FFFFFFFu) : ~u;
    return __expf(__uint_as_float(bb));
}

#define GETC(v4, kk) ((kk) == 0 ? (v4).x : (kk) == 1 ? (v4).y : (kk) == 2 ? (v4).z : (v4).w)

// ---------------- SGEMM: C[M][4096] = A[M][256] * B[256][4096] ----------------
__global__ void __launch_bounds__(256) k_sgemm(const float* __restrict__ A,
                                               const float* __restrict__ Bx, int mode) {
    const float* B = mode ? (const float*)g_attn : Bx;
    float* C = mode ? g_proj : g_qkv;
    __shared__ float As[64][17];
    __shared__ float Bs[16][128];
    int t = threadIdx.x;
    int bm = blockIdx.y * 64, bn = blockIdx.x * 128;
    int tr = t >> 4, tc = t & 15;
    int arow = t >> 2, akk = (t & 3) * 4;
    int brow = t >> 4, bcol = (t & 15) * 8;
    float acc[4][8];
#pragma unroll
    for (int i = 0; i < 4; i++)
#pragma unroll
        for (int j = 0; j < 8; j++) acc[i][j] = 0.f;
    for (int k0 = 0; k0 < 256; k0 += 16) {
        float4 a4 = *(const float4*)&A[(bm + arow) * 256 + k0 + akk];
        float4 b0 = *(const float4*)&B[(size_t)(k0 + brow) * N_ + bn + bcol];
        float4 b1 = *(const float4*)&B[(size_t)(k0 + brow) * N_ + bn + bcol + 4];
        __syncthreads();
        As[arow][akk + 0] = a4.x; As[arow][akk + 1] = a4.y;
        As[arow][akk + 2] = a4.z; As[arow][akk + 3] = a4.w;
        *(float4*)&Bs[brow][bcol] = b0;
        *(float4*)&Bs[brow][bcol + 4] = b1;
        __syncthreads();
#pragma unroll
        for (int k = 0; k < 16; k++) {
            float4 bv0 = *(const float4*)&Bs[k][tc * 4];
            float4 bv1 = *(const float4*)&Bs[k][64 + tc * 4];
#pragma unroll
            for (int i = 0; i < 4; i++) {
                float a = As[tr * 4 + i][k];
                acc[i][0] += a * bv0.x; acc[i][1] += a * bv0.y;
                acc[i][2] += a * bv0.z; acc[i][3] += a * bv0.w;
                acc[i][4] += a * bv1.x; acc[i][5] += a * bv1.y;
                acc[i][6] += a * bv1.z; acc[i][7] += a * bv1.w;
            }
        }
    }
#pragma unroll
    for (int i = 0; i < 4; i++) {
        size_t row = bm + tr * 4 + i;
        *(float4*)&C[row * N_ + bn + tc * 4] =
            make_float4(acc[i][0], acc[i][1], acc[i][2], acc[i][3]);
        *(float4*)&C[row * N_ + bn + 64 + tc * 4] =
            make_float4(acc[i][4], acc[i][5], acc[i][6], acc[i][7]);
    }
}

// ---- transpose [3C][N]: q -> [h][n][d] (l2norm), k -> [h][d][n] (l2norm), v -> [h][n][d]
__global__ void __launch_bounds__(256) k_prep() {
    int which = blockIdx.y;                         // 0=q 1=k 2=v
    int idx = blockIdx.x * 256 + threadIdx.x;       // h*4096+n
    int h = idx >> 12, n = idx & 4095;
    const float* src = g_qkv + (size_t)(which * 256 + h * 32) * N_ + n;
    float s[32], ss = 0.f;
#pragma unroll
    for (int d = 0; d < 32; d++) { s[d] = src[(size_t)d * N_]; ss += s[d] * s[d]; }
    float inv = 1.f;
    if (which < 2) inv = 1.f / fmaxf(sqrtf(ss), 1e-12f);
    if (which == 1) {           // K: store transposed [h][d][n]
#pragma unroll
        for (int d = 0; d < 32; d++)
            g_kT[(size_t)(h * 32 + d) * N_ + n] = s[d] * inv;
    } else {
        float* dst = (which == 0 ? g_q : g_v) + (size_t)idx * 32;
#pragma unroll
        for (int d = 0; d < 32; d++) dst[d] = s[d] * inv;
    }
}

// ---------------- QK GEMM: S[h][row][key] = umap(clamp(q.k * scale)) ----------------
__global__ void __launch_bounds__(256) k_qk() {
    __shared__ float Qs[64 * 36];
    __shared__ float Ks[32 * 132];
    int t = threadIdx.x;
    int h = blockIdx.z;
    int i0 = blockIdx.y * 64;
    int j0 = blockIdx.x * 128;

    const float4* qsrc = (const float4*)(g_q + ((size_t)h * N_ + i0) * HD);
#pragma unroll
    for (int q = 0; q < 2; q++) {
        int idx = q * 256 + t;
        int row = idx >> 3, d4 = idx & 7;
        *(float4*)&Qs[row * 36 + d4 * 4] = qsrc[idx];
    }
#pragma unroll
    for (int q = 0; q < 4; q++) {
        int idx = q * 256 + t;
        int d = idx >> 5, k4 = idx & 31;
        *(float4*)&Ks[d * 132 + k4 * 4] =
            *(const float4*)(g_kT + (size_t)(h * HD + d) * N_ + j0 + k4 * 4);
    }
    __syncthreads();

    int tr = t >> 4, tc = t & 15;
    float acc[4][8];
#pragma unroll
    for (int i = 0; i < 4; i++)
#pragma unroll
        for (int j = 0; j < 8; j++) acc[i][j] = 0.f;

#pragma unroll
    for (int dc = 0; dc < 8; dc++) {
        float4 b0[4], b1[4];
#pragma unroll
        for (int j = 0; j < 4; j++) {
            b0[j] = *(float4*)&Ks[(dc * 4 + j) * 132 + tc * 4];
            b1[j] = *(float4*)&Ks[(dc * 4 + j) * 132 + 64 + tc * 4];
        }
#pragma unroll
        for (int i = 0; i < 4; i++) {
            float4 a = *(float4*)&Qs[(tr * 4 + i) * 36 + dc * 4];
#pragma unroll
            for (int kk = 0; kk < 4; kk++) {
                acc[i][kk]     += a.x * GETC(b0[0], kk) + a.y * GETC(b0[1], kk)
                                + a.z * GETC(b0[2], kk) + a.w * GETC(b0[3], kk);
                acc[i][4 + kk] += a.x * GETC(b1[0], kk) + a.y * GETC(b1[1], kk)
                                + a.z * GETC(b1[2], kk) + a.w * GETC(b1[3], kk);
            }
        }
    }

#pragma unroll
    for (int i = 0; i < 4; i++) {
        int row = i0 + tr * 4 + i;
        size_t base = ((size_t)h * N_ + row) * N_ + j0;
        uint4 o0, o1;
        o0.x = umap_score(acc[i][0]); o0.y = umap_score(acc[i][1]);
        o0.z = umap_score(acc[i][2]); o0.w = umap_score(acc[i][3]);
        o1.x = umap_score(acc[i][4]); o1.y = umap_score(acc[i][5]);
        o1.z = umap_score(acc[i][6]); o1.w = umap_score(acc[i][7]);
        *(uint4*)&g_S[base + tc * 4] = o0;
        *(uint4*)&g_S[base + 64 + tc * 4] = o1;
    }
}

// ---------------- per-row select: exact k-th threshold + exp-sum ----------------
// One row per CTA. Pass A: 2048-bin histogram on bits[31:21] (spread bins ->
// plain atomics, no match_any). Passes B/C/D: prefix-filtered 8/8/5-bit passes
// where the atomic executes only for the few prefix-matching elements.
__global__ void __launch_bounds__(256) k_sel() {
    __shared__ unsigned su[4096];
    __shared__ int hist[2048];
    __shared__ unsigned s_pref;
    __shared__ int s_want;
    __shared__ float s_red[8];
    __shared__ int s_wsum[8];
    int b = blockIdx.x;                  // h*4096 + row
    int t = threadIdx.x, l = t & 31, w = t >> 5;

    const uint4* src = (const uint4*)(g_S + (size_t)b * N_);
#pragma unroll
    for (int q = 0; q < 4; q++)
        ((uint4*)su)[q * 256 + t] = src[q * 256 + t];
#pragma unroll
    for (int q = 0; q < 8; q++) hist[q * 256 + t] = 0;
    __syncthreads();

    // ---- Pass A: 11-bit histogram (bits 31:21), spread bins
#pragma unroll
    for (int q = 0; q < 4; q++) {
        unsigned uu[4];
#pragma unroll
        for (int x = 0; x < 4; x++) uu[x] = su[t + q * 1024 + x * 256];
#pragma unroll
        for (int x = 0; x < 4; x++)
            atomicAdd(&hist[uu[x] >> 21], 1);
    }
    __syncthreads();
    // block-wide descending suffix scan over 2048 bins; thread t owns 8 bins
    {
        int base = 2047 - t * 8;
        int cnt[8]; int local = 0;
#pragma unroll
        for (int i = 0; i < 8; i++) { cnt[i] = hist[base - i]; local += cnt[i]; }
        int pre = local;
#pragma unroll
        for (int o = 1; o < 32; o <<= 1) {
            int x = __shfl_up_sync(0xffffffffu, pre, o);
            if (l >= o) pre += x;
        }
        if (l == 31) s_wsum[w] = pre;
        __syncthreads();
        int woff = 0;
        for (int i = 0; i < w; i++) woff += s_wsum[i];
        int cum_before = woff + pre - local;
        if (cum_before < KNUM && cum_before + local >= KNUM) {
            int rem = KNUM - cum_before, c = 0;
#pragma unroll
            for (int i = 0; i < 8; i++) {
                if (c + cnt[i] >= rem) {
                    s_pref = (unsigned)(base - i);
                    s_want = rem - c;
                    break;
                }
                c += cnt[i];
            }
        }
    }
    __syncthreads();

    // ---- Passes B/C/D: bits [20:13], [12:5], [4:0]; prefix-filtered
    const int shv[3] = {13, 5, 0};
    const int wdv[3] = {8, 8, 5};
    for (int pp = 0; pp < 3; pp++) {
        int sh = shv[pp];
        int wd = wdv[pp];
        int nb = 1 << wd;
        for (int q = t; q < nb; q += 256) hist[q] = 0;
        __syncthreads();
        unsigned prefix = s_pref;
        int psh = sh + wd;               // bits above the current field
#pragma unroll
        for (int q = 0; q < 4; q++) {
            unsigned uu[4];
#pragma unroll
            for (int x = 0; x < 4; x++) uu[x] = su[t + q * 1024 + x * 256];
#pragma unroll
            for (int x = 0; x < 4; x++) {
                unsigned u = uu[x];
                if ((u >> psh) == prefix)
                    atomicAdd(&hist[(u >> sh) & (nb - 1)], 1);
            }
        }
        __syncthreads();
        if (w == 0) {                    // warp-parallel descending scan
            int want = s_want;
            int per = nb >> 5;           // 8 or 1 bins per lane
            int base2 = nb - 1 - l * per;
            int cnt[8]; int local = 0;
            for (int i = 0; i < per; i++) { cnt[i] = hist[base2 - i]; local += cnt[i]; }
            int pre = local;
#pragma unroll
            for (int o = 1; o < 32; o <<= 1) {
                int x = __shfl_up_sync(0xffffffffu, pre, o);
                if (l >= o) pre += x;
            }
            int cum_before = pre - local;
            if (cum_before < want && cum_before + local >= want) {
                int rem = want - cum_before, c = 0;
                for (int i = 0; i < per; i++) {
                    if (c + cnt[i] >= rem) {
                        s_pref = (s_pref << wd) | (unsigned)(base2 - i);
                        s_want = rem - c;
                        break;
                    }
                    c += cnt[i];
                }
            }
        }
        __syncthreads();
    }
    unsigned T = s_pref;                 // full 32-bit u-value of the k-th largest

    // ---- exp-sum over kept elements
    float sum = 0.f;
#pragma unroll
    for (int q = 0; q < 4; q++) {
        unsigned uu[4];
#pragma unroll
        for (int x = 0; x < 4; x++) uu[x] = su[t + q * 1024 + x * 256];
#pragma unroll
        for (int x = 0; x < 4; x++) {
            unsigned u = uu[x];
            if (u >= T) {
                unsigned bb = (u & 0x80000000u) ? (u & 0x7FFFFFFFu) : ~u;
                sum += __expf(__uint_as_float(bb));
            }
        }
    }
#pragma unroll
    for (int o = 16; o; o >>= 1) sum += __shfl_xor_sync(0xffffffffu, sum, o);
    if (l == 0) s_red[w] = sum;
    __syncthreads();
    if (t == 0) {
        float tot = 0.f;
#pragma unroll
        for (int i = 0; i < 8; i++) tot += s_red[i];
        g_T[b] = T;
        g_Inv[b] = 1.f / tot;
    }
}

// ---------------- AV GEMM: out = softmax(P) * V ----------------
#define AVP_OFF 0                        // P [128][132]
#define AVV_OFF (128 * 132)              // V [128][36]
#define AVT_OFF (AVV_OFF + 128 * 36)     // T [128] (uint)
#define AVI_OFF (AVT_OFF + 128)          // Inv [128]
#define AV_TOT  (AVI_OFF + 128)          // 21760 floats = 87040 bytes

__global__ void __launch_bounds__(256, 2) k_av() {
    extern __shared__ float avs[];
    float*    P    = avs + AVP_OFF;
    float*    V    = avs + AVV_OFF;
    unsigned* sT   = (unsigned*)(avs + AVT_OFF);
    float*    sInv = avs + AVI_OFF;

    int t = threadIdx.x;
    int h = blockIdx.y;
    int r0 = blockIdx.x * 128;
    int ks = t >> 7;                     // key half (0/1)
    int u7 = t & 127;
    int w4 = u7 >> 5;
    int lane = u7 & 31;
    int row_lo = lane & 3;
    int dg = lane >> 2;

    if (t < 128) {
        sT[t]   = g_T[h * N_ + r0 + t];
        sInv[t] = g_Inv[h * N_ + r0 + t];
    }

    float acc[8][4];
#pragma unroll
    for (int i = 0; i < 8; i++)
#pragma unroll
        for (int d = 0; d < 4; d++) acc[i][d] = 0.f;

    const unsigned* Sbase = g_S + ((size_t)h * N_ + r0) * N_;
    const float4* Vsrc = (const float4*)(g_v + (size_t)h * N_ * HD);

    for (int m0 = 0; m0 < N_; m0 += 128) {
        __syncthreads();
#pragma unroll
        for (int q = 0; q < 16; q++) {
            int idx = q * 256 + t;
            int row = idx >> 5, k4 = idx & 31;
            uint4 u4 = *(const uint4*)&Sbase[(size_t)row * N_ + m0 + k4 * 4];
            unsigned Tr = sT[row];
            float4 p4;
            p4.x = udecode_p(u4.x, Tr);
            p4.y = udecode_p(u4.y, Tr);
            p4.z = udecode_p(u4.z, Tr);
            p4.w = udecode_p(u4.w, Tr);
            *(float4*)&P[row * 132 + k4 * 4] = p4;
        }
#pragma unroll
        for (int q = 0; q < 4; q++) {
            int idx = q * 256 + t;
            int key = idx >> 3, d4 = idx & 7;
            *(float4*)&V[key * 36 + d4 * 4] = Vsrc[(size_t)(m0 + key) * 8 + d4];
        }
        __syncthreads();
        int kb = ks * 64;
        for (int m = 0; m < 64; m += 4) {
            float4 v0 = *(float4*)&V[(kb + m + 0) * 36 + dg * 4];
            float4 v1 = *(float4*)&V[(kb + m + 1) * 36 + dg * 4];
            float4 v2 = *(float4*)&V[(kb + m + 2) * 36 + dg * 4];
            float4 v3 = *(float4*)&V[(kb + m + 3) * 36 + dg * 4];
#pragma unroll
            for (int i = 0; i < 8; i++) {
                int R = w4 * 32 + row_lo + 4 * i;
                float4 p = *(float4*)&P[R * 132 + kb + m];
                acc[i][0] += p.x * v0.x + p.y * v1.x + p.z * v2.x + p.w * v3.x;
                acc[i][1] += p.x * v0.y + p.y * v1.y + p.z * v2.y + p.w * v3.y;
                acc[i][2] += p.x * v0.z + p.y * v1.z + p.z * v2.z + p.w * v3.z;
                acc[i][3] += p.x * v0.w + p.y * v1.w + p.z * v2.w + p.w * v3.w;
            }
        }
    }

    __syncthreads();
    float* red = avs;                    // 128 x 36
    if (ks == 1) {
#pragma unroll
        for (int i = 0; i < 8; i++) {
            int R = w4 * 32 + row_lo + 4 * i;
            *(float4*)&red[R * 36 + dg * 4] =
                make_float4(acc[i][0], acc[i][1], acc[i][2], acc[i][3]);
        }
    }
    __syncthreads();
    if (ks == 0) {
#pragma unroll
        for (int i = 0; i < 8; i++) {
            int R = w4 * 32 + row_lo + 4 * i;
            float4 o = *(float4*)&red[R * 36 + dg * 4];
            float inv = sInv[R];
            int row = r0 + R;
            g_attn[(size_t)(h * 32 + dg * 4 + 0) * N_ + row] = (acc[i][0] + o.x) * inv;
            g_attn[(size_t)(h * 32 + dg * 4 + 1) * N_ + row] = (acc[i][1] + o.y) * inv;
            g_attn[(size_t)(h * 32 + dg * 4 + 2) * N_ + row] = (acc[i][2] + o.z) * inv;
            g_attn[(size_t)(h * 32 + dg * 4 + 3) * N_ + row] = (acc[i][3] + o.w) * inv;
        }
    }
}

// ---------------- GroupNorm(32 groups) ----------------
__global__ void __launch_bounds__(256) k_gn(const float* __restrict__ gamma,
                                            const float* __restrict__ beta,
                                            float* __restrict__ out) {
    __shared__ float rs[2][8];
    int g = blockIdx.x, t = threadIdx.x;
    const float* src = g_proj + (size_t)g * 8 * N_;
    float sum = 0.f, sq = 0.f;
    for (int i = t; i < 8 * N_; i += 256) { float v = src[i]; sum += v; sq += v * v; }
#pragma unroll
    for (int o = 16; o; o >>= 1) {
        sum += __shfl_xor_sync(0xffffffffu, sum, o);
        sq  += __shfl_xor_sync(0xffffffffu, sq, o);
    }
    if ((t & 31) == 0) { rs[0][t >> 5] = sum; rs[1][t >> 5] = sq; }
    __syncthreads();
    if (t < 32) {
        float a = (t < 8) ? rs[0][t] : 0.f;
        float b = (t < 8) ? rs[1][t] : 0.f;
#pragma unroll
        for (int o = 4; o; o >>= 1) {
            a += __shfl_xor_sync(0xffffffffu, a, o);
            b += __shfl_xor_sync(0xffffffffu, b, o);
        }
        if (t == 0) { rs[0][0] = a; rs[1][0] = b; }
    }
    __syncthreads();
    float inv_m = 1.f / (8.f * N_);
    float mean = rs[0][0] * inv_m;
    float var = rs[1][0] * inv_m - mean * mean;
    float rstd = rsqrtf(var + 1e-6f);
    for (int i = t; i < 8 * N_; i += 256) {
        int c = g * 8 + (i >> 12);
        out[(size_t)g * 8 * N_ + i] = (src[i] - mean) * rstd * gamma[c] + beta[c];
    }
}

extern "C" void kernel_launch(void* const* d_in, const int* in_sizes, int n_in,
                              void* d_out, int out_size) {
    (void)in_sizes; (void)n_in; (void)out_size;
    const float* x      = (const float*)d_in[0];
    const float* w_qkv  = (const float*)d_in[1];
    const float* w_proj = (const float*)d_in[2];
    const float* gamma  = (const float*)d_in[3];
    const float* beta   = (const float*)d_in[4];
    float* out = (float*)d_out;

    cudaFuncSetAttribute(k_av, cudaFuncAttributeMaxDynamicSharedMemorySize,
                         AV_TOT * (int)sizeof(float));

    // harness issues 2 internal launches first; ncu -s 5 captures global
    // index 5 = my index 3 -> k_sel (verifying this round's fix).
    k_sgemm<<<dim3(32, 12), 256>>>(w_qkv, x, 0);               // my 0: qkv
    k_prep<<<dim3(128, 3), 256>>>();                            // my 1
    k_qk<<<dim3(32, 64, 8), 256>>>();                           // my 2
    k_sel<<<32768, 256>>>();                                    // my 3 (profiled)
    k_av<<<dim3(32, 8), 256, AV_TOT * sizeof(float)>>>();       // my 4
    k_sgemm<<<dim3(32, 4), 256>>>(w_proj, nullptr, 1);          // my 5: proj
    k_gn<<<32, 256>>>(gamma, beta, out);                        // my 6
}